// round 13
// baseline (speedup 1.0000x reference)
#include <cuda_runtime.h>
#include <cuda_fp16.h>
#include <math.h>
#include <cstdint>

#define SEQ 2048
#define HID 2048
#define KVD 512
#define QKVN 3072
#define WROWS 5120
#define NQH 32
#define NKH 8

// ---------------- scratch (no allocations allowed) ----------------
__device__ __half g_Axh[SEQ * HID];          // x fp16 hi
__device__ __half g_Axl[SEQ * HID];          // x fp16 lo
__device__ __half g_Qh[SEQ * HID];           // Q fp16 hi (post-rope, scaled)
__device__ __half g_Ql[SEQ * HID];           // Q fp16 lo
__device__ __half g_Ohf[SEQ * HID];
__device__ __half g_Olf[SEQ * HID];
__device__ __half g_Wh[WROWS * HID];         // transposed q|k|v|o weights, fp16
__device__ __half g_Kh[SEQ * KVD];           // K fp16 (post-rope)
__device__ __half g_Vh[SEQ * KVD];           // V fp16
__device__ float2 g_sc[SEQ * 32];            // sincos LUT

// ---------------- helpers ----------------
__device__ __forceinline__ uint32_t smem_u32(const void* p) {
    uint32_t a;
    asm("{ .reg .u64 t; cvta.to.shared.u64 t, %1; cvt.u32.u64 %0, t; }" : "=r"(a) : "l"(p));
    return a;
}

#define LDSM4(r0, r1, r2, r3, addr) \
    asm volatile("ldmatrix.sync.aligned.m8n8.x4.shared.b16 {%0,%1,%2,%3}, [%4];" \
        : "=r"(r0), "=r"(r1), "=r"(r2), "=r"(r3) : "r"(addr))

#define LDSM4T(r0, r1, r2, r3, addr) \
    asm volatile("ldmatrix.sync.aligned.m8n8.x4.trans.shared.b16 {%0,%1,%2,%3}, [%4];" \
        : "=r"(r0), "=r"(r1), "=r"(r2), "=r"(r3) : "r"(addr))

#define MMA16816F(d, a, b0, b1) \
    asm volatile("mma.sync.aligned.m16n8k16.row.col.f32.f16.f16.f32 " \
        "{%0,%1,%2,%3},{%4,%5,%6,%7},{%8,%9},{%0,%1,%2,%3};" \
        : "+f"((d)[0]), "+f"((d)[1]), "+f"((d)[2]), "+f"((d)[3]) \
        : "r"((a)[0]), "r"((a)[1]), "r"((a)[2]), "r"((a)[3]), "r"(b0), "r"(b1))

#define CP_ASYNC16(dst, src) \
    asm volatile("cp.async.cg.shared.global [%0], [%1], 16;" :: "r"(dst), "l"(src))
#define CP_COMMIT() asm volatile("cp.async.commit_group;" ::: "memory")
#define CP_WAIT0()  asm volatile("cp.async.wait_group 0;" ::: "memory")
#define CP_WAIT1()  asm volatile("cp.async.wait_group 1;" ::: "memory")

// ---------------- elementwise kernels ----------------
__device__ __forceinline__ void pack_hl16(float p0, float p1, uint32_t& hi, uint32_t& lo) {
    __half2 h = __floats2half2_rn(p0, p1);
    hi = *reinterpret_cast<uint32_t*>(&h);
    __half2 l = __floats2half2_rn(p0 - __half2float(__low2half(h)),
                                  p1 - __half2float(__high2half(h)));
    lo = *reinterpret_cast<uint32_t*>(&l);
}

__global__ __launch_bounds__(256) void convert_hl16(const float* __restrict__ X,
                                                    __half* __restrict__ hi,
                                                    __half* __restrict__ lo) {
    int i = blockIdx.x * 256 + threadIdx.x;
    float4 v = *(const float4*)(X + (size_t)i * 4);
    uint32_t h0, l0, h1, l1;
    pack_hl16(v.x, v.y, h0, l0);
    pack_hl16(v.z, v.w, h1, l1);
    *(uint2*)(hi + (size_t)i * 4) = make_uint2(h0, h1);
    *(uint2*)(lo + (size_t)i * 4) = make_uint2(l0, l1);
}

__global__ __launch_bounds__(256) void transpose_all16(const float* __restrict__ Wq,
                                                       const float* __restrict__ Wk,
                                                       const float* __restrict__ Wv,
                                                       const float* __restrict__ Wo,
                                                       __half* __restrict__ toh) {
    __shared__ float t[32][33];
    int bx = blockIdx.x;
    const float* W;
    int N, nblk, dstoff;
    if (bx < 64)       { W = Wq; N = HID; nblk = bx;      dstoff = 0; }
    else if (bx < 80)  { W = Wk; N = KVD; nblk = bx - 64; dstoff = HID; }
    else if (bx < 96)  { W = Wv; N = KVD; nblk = bx - 80; dstoff = HID + KVD; }
    else               { W = Wo; N = HID; nblk = bx - 96; dstoff = QKVN; }
    int tx = threadIdx.x & 31, ty = threadIdx.x >> 5;
    int k0 = blockIdx.y * 32, n0 = nblk * 32;
#pragma unroll
    for (int i = 0; i < 4; i++)
        t[ty + i * 8][tx] = W[(size_t)(k0 + ty + i * 8) * N + n0 + tx];
    __syncthreads();
#pragma unroll
    for (int i = 0; i < 4; i++) {
        float v = t[tx][ty + i * 8];
        toh[(size_t)(dstoff + n0 + ty + i * 8) * HID + k0 + tx] = __float2half_rn(v);
    }
}

__global__ __launch_bounds__(256) void sc_init(const float* __restrict__ inv_freq,
                                               float2* __restrict__ sc) {
    int i = blockIdx.x * 256 + threadIdx.x;
    int s = i >> 5, j = i & 31;
    float angle = (float)s * inv_freq[j];
    sc[i] = make_float2(sinf(angle), cosf(angle));
}

// ---------------- shared GEMM mainloop pieces ----------------
#define TILE_B 10240
#define BUF2_B 30720
#define G2_SMEM (2 * BUF2_B)
#define SPAD 132

__device__ __forceinline__ void tile_async(uint32_t dst, const void* src_,
                                           int ldk, int tid) {
    const __half* src = (const __half*)src_;
#pragma unroll
    for (int t = 0; t < 2; t++) {
        int i = tid + t * 256;
        int r = i >> 2, q = i & 3;
        CP_ASYNC16(dst + r * 80 + q * 16, src + (size_t)r * ldk + q * 8);
    }
}

// mainloop macro body shared by both GEMMs (fp16 2-pass, 128x128, occ2)
#define GEMM_MAINLOOP(Ahi, Alo, Bh, K)                                              \
    const int NC = (K) >> 5;                                                        \
    {                                                                               \
        const size_t ak = (size_t)m0 * (K);                                         \
        const size_t bk = (size_t)n0 * (K);                                         \
        tile_async(sb,              (Ahi) + ak, (K), tid);                          \
        tile_async(sb + TILE_B,     (Alo) + ak, (K), tid);                          \
        tile_async(sb + 2 * TILE_B, (Bh) + bk, (K), tid);                           \
        CP_COMMIT();                                                                \
    }                                                                               \
    for (int c = 0; c < NC; c++) {                                                  \
        CP_WAIT0();                                                                 \
        __syncthreads();                                                            \
        if (c + 1 < NC) {                                                           \
            const uint32_t nb = sb + ((c + 1) & 1) * BUF2_B;                        \
            const size_t ak = (size_t)m0 * (K) + (size_t)(c + 1) * 32;              \
            const size_t bk = (size_t)n0 * (K) + (size_t)(c + 1) * 32;              \
            tile_async(nb,              (Ahi) + ak, (K), tid);                      \
            tile_async(nb + TILE_B,     (Alo) + ak, (K), tid);                      \
            tile_async(nb + 2 * TILE_B, (Bh) + bk, (K), tid);                       \
            CP_COMMIT();                                                            \
        }                                                                           \
        const uint32_t base = sb + (c & 1) * BUF2_B;                                \
        _Pragma("unroll")                                                           \
        for (int ks = 0; ks < 32; ks += 16) {                                       \
            uint32_t ah[4][4], al[4][4], bh[2][4];                                  \
            const uint32_t aoff = (uint32_t)((wm + a_row) * 80 + (ks + a_kh * 8) * 2); \
            const uint32_t boff = (uint32_t)((wn + b_n) * 80 + (ks + b_kh * 8) * 2);   \
            _Pragma("unroll")                                                       \
            for (int mt = 0; mt < 4; mt++) {                                        \
                LDSM4(ah[mt][0], ah[mt][1], ah[mt][2], ah[mt][3],                   \
                      base + aoff + mt * 16 * 80);                                  \
                LDSM4(al[mt][0], al[mt][1], al[mt][2], al[mt][3],                   \
                      base + TILE_B + aoff + mt * 16 * 80);                         \
            }                                                                       \
            _Pragma("unroll")                                                       \
            for (int np = 0; np < 2; np++)                                          \
                LDSM4(bh[np][0], bh[np][1], bh[np][2], bh[np][3],                   \
                      base + 2 * TILE_B + boff + np * 16 * 80);                     \
            _Pragma("unroll")                                                       \
            for (int mt = 0; mt < 4; mt++)                                          \
                _Pragma("unroll")                                                   \
                for (int np = 0; np < 2; np++) {                                    \
                    MMA16816F(acc[mt][np * 2 + 0], ah[mt], bh[np][0], bh[np][1]);   \
                    MMA16816F(acc[mt][np * 2 + 1], ah[mt], bh[np][2], bh[np][3]);   \
                }                                                                   \
            _Pragma("unroll")                                                       \
            for (int mt = 0; mt < 4; mt++)                                          \
                _Pragma("unroll")                                                   \
                for (int np = 0; np < 2; np++) {                                    \
                    MMA16816F(acc[mt][np * 2 + 0], al[mt], bh[np][0], bh[np][1]);   \
                    MMA16816F(acc[mt][np * 2 + 1], al[mt], bh[np][2], bh[np][3]);   \
                }                                                                   \
        }                                                                           \
    }

// ---------------- QKV GEMM with fused rope/split epilogue ----------------
__global__ __launch_bounds__(256, 2) void gemm_qkv(
    const __half* __restrict__ Ahi, const __half* __restrict__ Alo,
    const __half* __restrict__ Bh,
    __half* __restrict__ Qh, __half* __restrict__ Ql,
    __half* __restrict__ Kh, __half* __restrict__ Vh,
    const float2* __restrict__ sc) {
    extern __shared__ char smem[];
    const uint32_t sb = smem_u32(smem);
    const int tid = threadIdx.x;
    const int w = tid >> 5;
    const int lane = tid & 31;
    const int wm = (w & 1) * 64;
    const int wn = (w >> 1) * 32;
    const int m0 = blockIdx.y * 128;
    const int n0 = blockIdx.x * 128;

    const int a_row = lane & 15;
    const int a_kh = (lane >> 4) & 1;
    const int b_n = (lane & 7) + ((lane >> 4) << 3);
    const int b_kh = (lane >> 3) & 1;

    float acc[4][4][4];
#pragma unroll
    for (int i = 0; i < 4; i++)
#pragma unroll
        for (int j = 0; j < 4; j++)
#pragma unroll
            for (int r = 0; r < 4; r++) acc[i][j][r] = 0.f;

    GEMM_MAINLOOP(Ahi, Alo, Bh, HID)

    const int g = lane >> 2, c2 = lane & 3;

    if (n0 >= HID + KVD) {
        // V region: plain fp16 convert, direct from registers
        const int vcol0 = n0 - (HID + KVD);
#pragma unroll
        for (int mt = 0; mt < 4; mt++) {
            const int row = m0 + wm + mt * 16 + g;
#pragma unroll
            for (int nt = 0; nt < 4; nt++) {
                const int col = vcol0 + wn + nt * 8 + c2 * 2;
                __half2 v0 = __floats2half2_rn(acc[mt][nt][0], acc[mt][nt][1]);
                __half2 v1 = __floats2half2_rn(acc[mt][nt][2], acc[mt][nt][3]);
                *(uint32_t*)&Vh[(size_t)row * KVD + col] = *reinterpret_cast<uint32_t*>(&v0);
                *(uint32_t*)&Vh[(size_t)(row + 8) * KVD + col] = *reinterpret_cast<uint32_t*>(&v1);
            }
        }
        return;
    }

    // Q or K region: rope via smem exchange (2 halves of 64 rows x 128 cols fp32)
    const bool isQ = (n0 < HID);
    const float scale = isQ ? 0.125f : 1.0f;
    float* st = (float*)smem;

#pragma unroll
    for (int h = 0; h < 2; h++) {
        __syncthreads();
        // stage acc[2h..2h+1] into smem [64][SPAD]
#pragma unroll
        for (int mt2 = 0; mt2 < 2; mt2++) {
            const int mt = 2 * h + mt2;
            const int sr = (w & 1) * 32 + mt2 * 16 + g;
#pragma unroll
            for (int nt = 0; nt < 4; nt++) {
                const int col = wn + nt * 8 + c2 * 2;
                st[sr * SPAD + col] = acc[mt][nt][0];
                st[sr * SPAD + col + 1] = acc[mt][nt][1];
                st[(sr + 8) * SPAD + col] = acc[mt][nt][2];
                st[(sr + 8) * SPAD + col + 1] = acc[mt][nt][3];
            }
        }
        __syncthreads();
        // rope + convert + write: 64 rows x 64 col-pairs
#pragma unroll
        for (int i = 0; i < 16; i++) {
            const int idx = tid + i * 256;
            const int sr = idx >> 6;
            const int col = (idx & 63) * 2;
            const int br = (sr < 32) ? h * 32 + sr : 64 + h * 32 + (sr - 32);
            const int s = m0 + br;
            const int hl = col & 63;
            const int j = hl & 31;
            const float2 sc0 = sc[s * 32 + j];
            const float2 sc1 = sc[s * 32 + j + 1];
            const float v0 = st[sr * SPAD + col], v1 = st[sr * SPAD + col + 1];
            float r0, r1;
            if (hl < 32) {
                const float b0 = st[sr * SPAD + col + 32], b1 = st[sr * SPAD + col + 33];
                r0 = (v0 * sc0.y + b0 * sc0.x) * scale;
                r1 = (v1 * sc1.y + b1 * sc1.x) * scale;
            } else {
                const float a0 = st[sr * SPAD + col - 32], a1 = st[sr * SPAD + col - 31];
                r0 = (a0 * sc0.x - v0 * sc0.y) * scale;
                r1 = (a1 * sc1.x - v1 * sc1.y) * scale;
            }
            if (isQ) {
                uint32_t hh, ll;
                pack_hl16(r0, r1, hh, ll);
                const size_t o = (size_t)s * HID + n0 + col;
                *(uint32_t*)&Qh[o] = hh;
                *(uint32_t*)&Ql[o] = ll;
            } else {
                __half2 v = __floats2half2_rn(r0, r1);
                *(uint32_t*)&Kh[(size_t)s * KVD + (n0 - HID) + col] =
                    *reinterpret_cast<uint32_t*>(&v);
            }
        }
    }
}

// ---------------- fp16 2-pass GEMM (O projection) ----------------
__global__ __launch_bounds__(256, 2) void gemm_mma2(
    const __half* __restrict__ Ahi, const __half* __restrict__ Alo,
    const __half* __restrict__ Bh,
    float* __restrict__ C, int M, int N, int K) {
    extern __shared__ char smem[];
    const uint32_t sb = smem_u32(smem);
    const int tid = threadIdx.x;
    const int w = tid >> 5;
    const int lane = tid & 31;
    const int wm = (w & 1) * 64;
    const int wn = (w >> 1) * 32;
    const int m0 = blockIdx.y * 128;
    const int n0 = blockIdx.x * 128;

    const int a_row = lane & 15;
    const int a_kh = (lane >> 4) & 1;
    const int b_n = (lane & 7) + ((lane >> 4) << 3);
    const int b_kh = (lane >> 3) & 1;

    float acc[4][4][4];
#pragma unroll
    for (int i = 0; i < 4; i++)
#pragma unroll
        for (int j = 0; j < 4; j++)
#pragma unroll
            for (int r = 0; r < 4; r++) acc[i][j][r] = 0.f;

    GEMM_MAINLOOP(Ahi, Alo, Bh, K)

    const int g = lane >> 2, c2 = lane & 3;
#pragma unroll
    for (int mt = 0; mt < 4; mt++) {
        const int row = m0 + wm + mt * 16 + g;
#pragma unroll
        for (int nt = 0; nt < 4; nt++) {
            const int col = n0 + wn + nt * 8 + c2 * 2;
            *(float2*)&C[(size_t)row * N + col] =
                make_float2(acc[mt][nt][0], acc[mt][nt][1]);
            *(float2*)&C[(size_t)(row + 8) * N + col] =
                make_float2(acc[mt][nt][2], acc[mt][nt][3]);
        }
    }
}

// ---------------- all-fp16 tensor-core flash attention (unchanged) ----------------
#define FQ_H 0
#define FQ_L 18432
#define FKV  36864
#define FKV_STRIDE 18432
#define F_SMEM 73728

__global__ __launch_bounds__(256, 2) void flash_mma(
    const __half* __restrict__ Qhi, const __half* __restrict__ Qlo,
    const __half* __restrict__ Kh, const __half* __restrict__ Vh,
    __half* __restrict__ Ohf, __half* __restrict__ Olf) {
    extern __shared__ char smem[];
    const uint32_t sb = smem_u32(smem);
    const int tid = threadIdx.x;
    const int lane = tid & 31;
    const int w = tid >> 5;
    const int ib = gridDim.x - 1 - blockIdx.x;
    const int qh = blockIdx.y;
    const int kh = qh >> 2;
    const int qbase = ib * 128;

#pragma unroll
    for (int i = 0; i < 8; i++) {
        int idx = tid + i * 256;
        int sub = idx >> 10, r = (idx >> 3) & 127, q = idx & 7;
        const __half* src = (sub ? Qlo : Qhi) + (size_t)(qbase + r) * HID + qh * 64 + q * 8;
        CP_ASYNC16(sb + sub * 18432 + r * 144 + q * 16, src);
    }
    CP_COMMIT();

#pragma unroll
    for (int i = 0; i < 4; i++) {
        int idx = tid + i * 256;
        int sub = idx >> 9, r = (idx >> 3) & 63, q = idx & 7;
        const __half* base = sub ? Vh : Kh;
        CP_ASYNC16(sb + FKV + sub * 9216 + r * 144 + q * 16,
                   base + (size_t)r * KVD + kh * 64 + q * 8);
    }
    CP_COMMIT();

    const int a_row = lane & 15, a_kh = lane >> 4;
    const int b_n = (lane & 7) + ((lane >> 4) << 3), b_kh = (lane >> 3) & 1;
    const int v_k = (lane & 7) + ((lane >> 3) & 1) * 8, v_n = (lane >> 4) * 8;
    const int g = lane >> 2, tg = lane & 3;

    float o[8][4];
#pragma unroll
    for (int nt = 0; nt < 8; nt++)
#pragma unroll
        for (int r = 0; r < 4; r++) o[nt][r] = 0.f;
    float m0 = -1e30f, m1 = -1e30f, l0 = 0.f, l1 = 0.f;

    const int jbmax = 2 * ib + 1;
    for (int jb = 0; jb <= jbmax; jb++) {
        const uint32_t kvb = sb + FKV + (jb & 1) * FKV_STRIDE;
        __syncthreads();
        if (jb < jbmax) {
            const uint32_t nb = sb + FKV + ((jb + 1) & 1) * FKV_STRIDE;
#pragma unroll
            for (int i = 0; i < 4; i++) {
                int idx = tid + i * 256;
                int sub = idx >> 9, r = (idx >> 3) & 63, q = idx & 7;
                const __half* base = sub ? Vh : Kh;
                CP_ASYNC16(nb + sub * 9216 + r * 144 + q * 16,
                           base + (size_t)((jb + 1) * 64 + r) * KVD + kh * 64 + q * 8);
            }
            CP_COMMIT();
            CP_WAIT1();
        } else {
            CP_WAIT0();
        }
        __syncthreads();

        float s[8][4];
#pragma unroll
        for (int nt = 0; nt < 8; nt++)
#pragma unroll
            for (int r = 0; r < 4; r++) s[nt][r] = 0.f;
#pragma unroll
        for (int kc = 0; kc < 4; kc++) {
            uint32_t ah[4], al[4];
            const uint32_t aoff = (w * 16 + a_row) * 144 + (kc * 16 + a_kh * 8) * 2;
            LDSM4(ah[0], ah[1], ah[2], ah[3], sb + FQ_H + aoff);
            LDSM4(al[0], al[1], al[2], al[3], sb + FQ_L + aoff);
#pragma unroll
            for (int n2p = 0; n2p < 2; n2p++) {
                uint32_t bh[2][4];
#pragma unroll
                for (int j = 0; j < 2; j++) {
                    const int n2 = n2p * 2 + j;
                    const uint32_t boff = (n2 * 16 + b_n) * 144 + (kc * 16 + b_kh * 8) * 2;
                    LDSM4(bh[j][0], bh[j][1], bh[j][2], bh[j][3], kvb + boff);
                }
#pragma unroll
                for (int j = 0; j < 2; j++) {
                    const int n2 = n2p * 2 + j;
                    MMA16816F(s[n2 * 2 + 0], ah, bh[j][0], bh[j][1]);
                    MMA16816F(s[n2 * 2 + 1], ah, bh[j][2], bh[j][3]);
                }
#pragma unroll
                for (int j = 0; j < 2; j++) {
                    const int n2 = n2p * 2 + j;
                    MMA16816F(s[n2 * 2 + 0], al, bh[j][0], bh[j][1]);
                    MMA16816F(s[n2 * 2 + 1], al, bh[j][2], bh[j][3]);
                }
            }
        }

        if (jb >= 2 * ib) {
            const int row0 = qbase + w * 16 + g;
            const int row1 = row0 + 8;
#pragma unroll
            for (int nt = 0; nt < 8; nt++) {
                const int col = jb * 64 + nt * 8 + tg * 2;
                if (col > row0) s[nt][0] = -1e30f;
                if (col + 1 > row0) s[nt][1] = -1e30f;
                if (col > row1) s[nt][2] = -1e30f;
                if (col + 1 > row1) s[nt][3] = -1e30f;
            }
        }

        float mx0 = -1e30f, mx1 = -1e30f;
#pragma unroll
        for (int nt = 0; nt < 8; nt++) {
            mx0 = fmaxf(mx0, fmaxf(s[nt][0], s[nt][1]));
            mx1 = fmaxf(mx1, fmaxf(s[nt][2], s[nt][3]));
        }
        mx0 = fmaxf(mx0, __shfl_xor_sync(0xffffffff, mx0, 1));
        mx0 = fmaxf(mx0, __shfl_xor_sync(0xffffffff, mx0, 2));
        mx1 = fmaxf(mx1, __shfl_xor_sync(0xffffffff, mx1, 1));
        mx1 = fmaxf(mx1, __shfl_xor_sync(0xffffffff, mx1, 2));
        const float mn0 = fmaxf(m0, mx0), mn1 = fmaxf(m1, mx1);
        const float al0 = __expf(m0 - mn0), al1 = __expf(m1 - mn1);
        m0 = mn0; m1 = mn1;

        float rs0 = 0.f, rs1 = 0.f;
#pragma unroll
        for (int nt = 0; nt < 8; nt++) {
            s[nt][0] = __expf(s[nt][0] - mn0);
            s[nt][1] = __expf(s[nt][1] - mn0);
            s[nt][2] = __expf(s[nt][2] - mn1);
            s[nt][3] = __expf(s[nt][3] - mn1);
            rs0 += s[nt][0] + s[nt][1];
            rs1 += s[nt][2] + s[nt][3];
            o[nt][0] *= al0; o[nt][1] *= al0;
            o[nt][2] *= al1; o[nt][3] *= al1;
        }
        rs0 += __shfl_xor_sync(0xffffffff, rs0, 1);
        rs0 += __shfl_xor_sync(0xffffffff, rs0, 2);
        rs1 += __shfl_xor_sync(0xffffffff, rs1, 1);
        rs1 += __shfl_xor_sync(0xffffffff, rs1, 2);
        l0 = l0 * al0 + rs0;
        l1 = l1 * al1 + rs1;

#pragma unroll
        for (int kc2 = 0; kc2 < 4; kc2++) {
            uint32_t aph[4], apl[4];
            pack_hl16(s[2 * kc2][0], s[2 * kc2][1], aph[0], apl[0]);
            pack_hl16(s[2 * kc2][2], s[2 * kc2][3], aph[1], apl[1]);
            pack_hl16(s[2 * kc2 + 1][0], s[2 * kc2 + 1][1], aph[2], apl[2]);
            pack_hl16(s[2 * kc2 + 1][2], s[2 * kc2 + 1][3], aph[3], apl[3]);
#pragma unroll
            for (int n2p = 0; n2p < 2; n2p++) {
                uint32_t vh[2][4];
#pragma unroll
                for (int j = 0; j < 2; j++) {
                    const int n2 = n2p * 2 + j;
                    const uint32_t voff = (kc2 * 16 + v_k) * 144 + (n2 * 16 + v_n) * 2;
                    LDSM4T(vh[j][0], vh[j][1], vh[j][2], vh[j][3], kvb + 9216 + voff);
                }
#pragma unroll
                for (int j = 0; j < 2; j++) {
                    const int n2 = n2p * 2 + j;
                    MMA16816F(o[n2 * 2 + 0], aph, vh[j][0], vh[j][1]);
                    MMA16816F(o[n2 * 2 + 1], aph, vh[j][2], vh[j][3]);
                }
#pragma unroll
                for (int j = 0; j < 2; j++) {
                    const int n2 = n2p * 2 + j;
                    MMA16816F(o[n2 * 2 + 0], apl, vh[j][0], vh[j][1]);
                    MMA16816F(o[n2 * 2 + 1], apl, vh[j][2], vh[j][3]);
                }
            }
        }
    }

    const float il0 = 1.0f / l0, il1 = 1.0f / l1;
    const int row0 = qbase + w * 16 + g;
#pragma unroll
    for (int nt = 0; nt < 8; nt++) {
        const int col = qh * 64 + nt * 8 + tg * 2;
        uint32_t h, l;
        pack_hl16(o[nt][0] * il0, o[nt][1] * il0, h, l);
        *(uint32_t*)&Ohf[(size_t)row0 * HID + col] = h;
        *(uint32_t*)&Olf[(size_t)row0 * HID + col] = l;
        pack_hl16(o[nt][2] * il1, o[nt][3] * il1, h, l);
        *(uint32_t*)&Ohf[(size_t)(row0 + 8) * HID + col] = h;
        *(uint32_t*)&Olf[(size_t)(row0 + 8) * HID + col] = l;
    }
}

// ---------------------------------------------------------------------------
extern "C" void kernel_launch(void* const* d_in, const int* in_sizes, int n_in,
                              void* d_out, int out_size) {
    const float* x        = (const float*)d_in[0];
    const float* q_proj   = (const float*)d_in[1];
    const float* k_proj   = (const float*)d_in[2];
    const float* v_proj   = (const float*)d_in[3];
    const float* o_proj   = (const float*)d_in[4];
    const float* inv_freq = (const float*)d_in[5];
    float* out = (float*)d_out;

    __half *Axh, *Axl, *Qh, *Ql, *Ohf, *Olf, *Wh, *Kh, *Vh;
    float2* sc;
    cudaGetSymbolAddress((void**)&Axh, g_Axh);
    cudaGetSymbolAddress((void**)&Axl, g_Axl);
    cudaGetSymbolAddress((void**)&Qh, g_Qh);
    cudaGetSymbolAddress((void**)&Ql, g_Ql);
    cudaGetSymbolAddress((void**)&Ohf, g_Ohf);
    cudaGetSymbolAddress((void**)&Olf, g_Olf);
    cudaGetSymbolAddress((void**)&Wh, g_Wh);
    cudaGetSymbolAddress((void**)&Kh, g_Kh);
    cudaGetSymbolAddress((void**)&Vh, g_Vh);
    cudaGetSymbolAddress((void**)&sc, g_sc);

    cudaFuncSetAttribute(gemm_qkv, cudaFuncAttributeMaxDynamicSharedMemorySize, G2_SMEM);
    cudaFuncSetAttribute(gemm_mma2, cudaFuncAttributeMaxDynamicSharedMemorySize, G2_SMEM);
    cudaFuncSetAttribute(flash_mma, cudaFuncAttributeMaxDynamicSharedMemorySize, F_SMEM);

    const int convBlocks = (SEQ * HID / 4) / 256;

    convert_hl16<<<convBlocks, 256>>>(x, Axh, Axl);
    transpose_all16<<<dim3(160, HID / 32), 256>>>(q_proj, k_proj, v_proj, o_proj, Wh);
    sc_init<<<SEQ * 32 / 256, 256>>>(inv_freq, sc);

    // fused QKV projection + rope + fp16 split (no fp32 intermediate)
    gemm_qkv<<<dim3(QKVN / 128, SEQ / 128), 256, G2_SMEM>>>(Axh, Axl, Wh,
                                                            Qh, Ql, Kh, Vh, sc);

    // all-fp16 flash attention
    flash_mma<<<dim3(SEQ / 128, NQH), 256, F_SMEM>>>(Qh, Ql, Kh, Vh, Ohf, Olf);

    // out = O @ o_proj (fp16 2-pass)
    gemm_mma2<<<dim3(HID / 128, SEQ / 128), 256, G2_SMEM>>>(Ohf, Olf, Wh + (size_t)QKVN * HID,
                                                            out, SEQ, HID, HID);
}

// round 14
// speedup vs baseline: 1.0724x; 1.0724x over previous
#include <cuda_runtime.h>
#include <cuda_fp16.h>
#include <math.h>
#include <cstdint>

#define SEQ 2048
#define HID 2048
#define KVD 512
#define QKVN 3072
#define WROWS 5120
#define NQH 32
#define NKH 8

// ---------------- scratch (no allocations allowed) ----------------
__device__ __half g_Axh[SEQ * HID];          // x fp16 hi
__device__ __half g_Axl[SEQ * HID];          // x fp16 lo
__device__ __half g_Qh[SEQ * HID];           // Q fp16 (post-rope, scaled)
__device__ __half g_Ohf[SEQ * HID];
__device__ __half g_Olf[SEQ * HID];
__device__ __half g_Wh[WROWS * HID];         // transposed q|k|v|o weights, fp16
__device__ __half g_Kh[SEQ * KVD];           // K fp16 (post-rope)
__device__ __half g_Vh[SEQ * KVD];           // V fp16
__device__ float2 g_sc[SEQ * 32];            // sincos LUT

// ---------------- helpers ----------------
__device__ __forceinline__ uint32_t smem_u32(const void* p) {
    uint32_t a;
    asm("{ .reg .u64 t; cvta.to.shared.u64 t, %1; cvt.u32.u64 %0, t; }" : "=r"(a) : "l"(p));
    return a;
}

#define LDSM4(r0, r1, r2, r3, addr) \
    asm volatile("ldmatrix.sync.aligned.m8n8.x4.shared.b16 {%0,%1,%2,%3}, [%4];" \
        : "=r"(r0), "=r"(r1), "=r"(r2), "=r"(r3) : "r"(addr))

#define LDSM4T(r0, r1, r2, r3, addr) \
    asm volatile("ldmatrix.sync.aligned.m8n8.x4.trans.shared.b16 {%0,%1,%2,%3}, [%4];" \
        : "=r"(r0), "=r"(r1), "=r"(r2), "=r"(r3) : "r"(addr))

#define MMA16816F(d, a, b0, b1) \
    asm volatile("mma.sync.aligned.m16n8k16.row.col.f32.f16.f16.f32 " \
        "{%0,%1,%2,%3},{%4,%5,%6,%7},{%8,%9},{%0,%1,%2,%3};" \
        : "+f"((d)[0]), "+f"((d)[1]), "+f"((d)[2]), "+f"((d)[3]) \
        : "r"((a)[0]), "r"((a)[1]), "r"((a)[2]), "r"((a)[3]), "r"(b0), "r"(b1))

#define CP_ASYNC16(dst, src) \
    asm volatile("cp.async.cg.shared.global [%0], [%1], 16;" :: "r"(dst), "l"(src))
#define CP_COMMIT() asm volatile("cp.async.commit_group;" ::: "memory")
#define CP_WAIT0()  asm volatile("cp.async.wait_group 0;" ::: "memory")
#define CP_WAIT1()  asm volatile("cp.async.wait_group 1;" ::: "memory")

// ---------------- elementwise kernels ----------------
__device__ __forceinline__ void pack_hl16(float p0, float p1, uint32_t& hi, uint32_t& lo) {
    __half2 h = __floats2half2_rn(p0, p1);
    hi = *reinterpret_cast<uint32_t*>(&h);
    __half2 l = __floats2half2_rn(p0 - __half2float(__low2half(h)),
                                  p1 - __half2float(__high2half(h)));
    lo = *reinterpret_cast<uint32_t*>(&l);
}

__global__ __launch_bounds__(256) void convert_hl16(const float* __restrict__ X,
                                                    __half* __restrict__ hi,
                                                    __half* __restrict__ lo) {
    int i = blockIdx.x * 256 + threadIdx.x;
    float4 v = *(const float4*)(X + (size_t)i * 4);
    uint32_t h0, l0, h1, l1;
    pack_hl16(v.x, v.y, h0, l0);
    pack_hl16(v.z, v.w, h1, l1);
    *(uint2*)(hi + (size_t)i * 4) = make_uint2(h0, h1);
    *(uint2*)(lo + (size_t)i * 4) = make_uint2(l0, l1);
}

__global__ __launch_bounds__(256) void transpose_all16(const float* __restrict__ Wq,
                                                       const float* __restrict__ Wk,
                                                       const float* __restrict__ Wv,
                                                       const float* __restrict__ Wo,
                                                       __half* __restrict__ toh) {
    __shared__ float t[32][33];
    int bx = blockIdx.x;
    const float* W;
    int N, nblk, dstoff;
    if (bx < 64)       { W = Wq; N = HID; nblk = bx;      dstoff = 0; }
    else if (bx < 80)  { W = Wk; N = KVD; nblk = bx - 64; dstoff = HID; }
    else if (bx < 96)  { W = Wv; N = KVD; nblk = bx - 80; dstoff = HID + KVD; }
    else               { W = Wo; N = HID; nblk = bx - 96; dstoff = QKVN; }
    int tx = threadIdx.x & 31, ty = threadIdx.x >> 5;
    int k0 = blockIdx.y * 32, n0 = nblk * 32;
#pragma unroll
    for (int i = 0; i < 4; i++)
        t[ty + i * 8][tx] = W[(size_t)(k0 + ty + i * 8) * N + n0 + tx];
    __syncthreads();
#pragma unroll
    for (int i = 0; i < 4; i++) {
        float v = t[tx][ty + i * 8];
        toh[(size_t)(dstoff + n0 + ty + i * 8) * HID + k0 + tx] = __float2half_rn(v);
    }
}

__global__ __launch_bounds__(256) void sc_init(const float* __restrict__ inv_freq,
                                               float2* __restrict__ sc) {
    int i = blockIdx.x * 256 + threadIdx.x;
    int s = i >> 5, j = i & 31;
    float angle = (float)s * inv_freq[j];
    sc[i] = make_float2(sinf(angle), cosf(angle));
}

// ---------------- shared GEMM mainloop ----------------
#define TILE_B 10240
#define BUF2_B 30720
#define G2_SMEM (2 * BUF2_B)
#define SPAD 132

__device__ __forceinline__ void tile_async(uint32_t dst, const void* src_,
                                           int ldk, int tid) {
    const __half* src = (const __half*)src_;
#pragma unroll
    for (int t = 0; t < 2; t++) {
        int i = tid + t * 256;
        int r = i >> 2, q = i & 3;
        CP_ASYNC16(dst + r * 80 + q * 16, src + (size_t)r * ldk + q * 8);
    }
}

#define GEMM_MAINLOOP(Ahi, Alo, Bh, K)                                              \
    const int NC = (K) >> 5;                                                        \
    {                                                                               \
        const size_t ak = (size_t)m0 * (K);                                         \
        const size_t bk = (size_t)n0 * (K);                                         \
        tile_async(sb,              (Ahi) + ak, (K), tid);                          \
        tile_async(sb + TILE_B,     (Alo) + ak, (K), tid);                          \
        tile_async(sb + 2 * TILE_B, (Bh) + bk, (K), tid);                           \
        CP_COMMIT();                                                                \
    }                                                                               \
    for (int c = 0; c < NC; c++) {                                                  \
        CP_WAIT0();                                                                 \
        __syncthreads();                                                            \
        if (c + 1 < NC) {                                                           \
            const uint32_t nb = sb + ((c + 1) & 1) * BUF2_B;                        \
            const size_t ak = (size_t)m0 * (K) + (size_t)(c + 1) * 32;              \
            const size_t bk = (size_t)n0 * (K) + (size_t)(c + 1) * 32;              \
            tile_async(nb,              (Ahi) + ak, (K), tid);                      \
            tile_async(nb + TILE_B,     (Alo) + ak, (K), tid);                      \
            tile_async(nb + 2 * TILE_B, (Bh) + bk, (K), tid);                       \
            CP_COMMIT();                                                            \
        }                                                                           \
        const uint32_t base = sb + (c & 1) * BUF2_B;                                \
        _Pragma("unroll")                                                           \
        for (int ks = 0; ks < 32; ks += 16) {                                       \
            uint32_t ah[4][4], al[4][4], bh[2][4];                                  \
            const uint32_t aoff = (uint32_t)((wm + a_row) * 80 + (ks + a_kh * 8) * 2); \
            const uint32_t boff = (uint32_t)((wn + b_n) * 80 + (ks + b_kh * 8) * 2);   \
            _Pragma("unroll")                                                       \
            for (int mt = 0; mt < 4; mt++) {                                        \
                LDSM4(ah[mt][0], ah[mt][1], ah[mt][2], ah[mt][3],                   \
                      base + aoff + mt * 16 * 80);                                  \
                LDSM4(al[mt][0], al[mt][1], al[mt][2], al[mt][3],                   \
                      base + TILE_B + aoff + mt * 16 * 80);                         \
            }                                                                       \
            _Pragma("unroll")                                                       \
            for (int np = 0; np < 2; np++)                                          \
                LDSM4(bh[np][0], bh[np][1], bh[np][2], bh[np][3],                   \
                      base + 2 * TILE_B + boff + np * 16 * 80);                     \
            _Pragma("unroll")                                                       \
            for (int mt = 0; mt < 4; mt++)                                          \
                _Pragma("unroll")                                                   \
                for (int np = 0; np < 2; np++) {                                    \
                    MMA16816F(acc[mt][np * 2 + 0], ah[mt], bh[np][0], bh[np][1]);   \
                    MMA16816F(acc[mt][np * 2 + 1], ah[mt], bh[np][2], bh[np][3]);   \
                }                                                                   \
            _Pragma("unroll")                                                       \
            for (int mt = 0; mt < 4; mt++)                                          \
                _Pragma("unroll")                                                   \
                for (int np = 0; np < 2; np++) {                                    \
                    MMA16816F(acc[mt][np * 2 + 0], al[mt], bh[np][0], bh[np][1]);   \
                    MMA16816F(acc[mt][np * 2 + 1], al[mt], bh[np][2], bh[np][3]);   \
                }                                                                   \
        }                                                                           \
    }

// ---------------- QKV GEMM with fused rope/split epilogue ----------------
__global__ __launch_bounds__(256, 2) void gemm_qkv(
    const __half* __restrict__ Ahi, const __half* __restrict__ Alo,
    const __half* __restrict__ Bh,
    __half* __restrict__ Qh, __half* __restrict__ Kh, __half* __restrict__ Vh,
    const float2* __restrict__ sc) {
    extern __shared__ char smem[];
    const uint32_t sb = smem_u32(smem);
    const int tid = threadIdx.x;
    const int w = tid >> 5;
    const int lane = tid & 31;
    const int wm = (w & 1) * 64;
    const int wn = (w >> 1) * 32;
    const int m0 = blockIdx.y * 128;
    const int n0 = blockIdx.x * 128;

    const int a_row = lane & 15;
    const int a_kh = (lane >> 4) & 1;
    const int b_n = (lane & 7) + ((lane >> 4) << 3);
    const int b_kh = (lane >> 3) & 1;

    float acc[4][4][4];
#pragma unroll
    for (int i = 0; i < 4; i++)
#pragma unroll
        for (int j = 0; j < 4; j++)
#pragma unroll
            for (int r = 0; r < 4; r++) acc[i][j][r] = 0.f;

    GEMM_MAINLOOP(Ahi, Alo, Bh, HID)

    const int g = lane >> 2, c2 = lane & 3;

    if (n0 >= HID + KVD) {
        const int vcol0 = n0 - (HID + KVD);
#pragma unroll
        for (int mt = 0; mt < 4; mt++) {
            const int row = m0 + wm + mt * 16 + g;
#pragma unroll
            for (int nt = 0; nt < 4; nt++) {
                const int col = vcol0 + wn + nt * 8 + c2 * 2;
                __half2 v0 = __floats2half2_rn(acc[mt][nt][0], acc[mt][nt][1]);
                __half2 v1 = __floats2half2_rn(acc[mt][nt][2], acc[mt][nt][3]);
                *(uint32_t*)&Vh[(size_t)row * KVD + col] = *reinterpret_cast<uint32_t*>(&v0);
                *(uint32_t*)&Vh[(size_t)(row + 8) * KVD + col] = *reinterpret_cast<uint32_t*>(&v1);
            }
        }
        return;
    }

    // Q or K region: rope via smem exchange (2 halves of 64 rows x 128 cols fp32)
    const bool isQ = (n0 < HID);
    const float scale = isQ ? 0.125f : 1.0f;
    float* st = (float*)smem;

#pragma unroll
    for (int h = 0; h < 2; h++) {
        __syncthreads();
#pragma unroll
        for (int mt2 = 0; mt2 < 2; mt2++) {
            const int mt = 2 * h + mt2;
            const int sr = (w & 1) * 32 + mt2 * 16 + g;
#pragma unroll
            for (int nt = 0; nt < 4; nt++) {
                const int col = wn + nt * 8 + c2 * 2;
                st[sr * SPAD + col] = acc[mt][nt][0];
                st[sr * SPAD + col + 1] = acc[mt][nt][1];
                st[(sr + 8) * SPAD + col] = acc[mt][nt][2];
                st[(sr + 8) * SPAD + col + 1] = acc[mt][nt][3];
            }
        }
        __syncthreads();
#pragma unroll
        for (int i = 0; i < 16; i++) {
            const int idx = tid + i * 256;
            const int sr = idx >> 6;
            const int col = (idx & 63) * 2;
            const int br = (sr < 32) ? h * 32 + sr : 64 + h * 32 + (sr - 32);
            const int s = m0 + br;
            const int hl = col & 63;
            const int j = hl & 31;
            const float2 sc0 = sc[s * 32 + j];
            const float2 sc1 = sc[s * 32 + j + 1];
            const float v0 = st[sr * SPAD + col], v1 = st[sr * SPAD + col + 1];
            float r0, r1;
            if (hl < 32) {
                const float b0 = st[sr * SPAD + col + 32], b1 = st[sr * SPAD + col + 33];
                r0 = (v0 * sc0.y + b0 * sc0.x) * scale;
                r1 = (v1 * sc1.y + b1 * sc1.x) * scale;
            } else {
                const float a0 = st[sr * SPAD + col - 32], a1 = st[sr * SPAD + col - 31];
                r0 = (a0 * sc0.x - v0 * sc0.y) * scale;
                r1 = (a1 * sc1.x - v1 * sc1.y) * scale;
            }
            __half2 v = __floats2half2_rn(r0, r1);
            if (isQ) {
                *(uint32_t*)&Qh[(size_t)s * HID + n0 + col] = *reinterpret_cast<uint32_t*>(&v);
            } else {
                *(uint32_t*)&Kh[(size_t)s * KVD + (n0 - HID) + col] =
                    *reinterpret_cast<uint32_t*>(&v);
            }
        }
    }
}

// ---------------- fp16 2-pass GEMM (O projection) ----------------
__global__ __launch_bounds__(256, 2) void gemm_mma2(
    const __half* __restrict__ Ahi, const __half* __restrict__ Alo,
    const __half* __restrict__ Bh,
    float* __restrict__ C, int M, int N, int K) {
    extern __shared__ char smem[];
    const uint32_t sb = smem_u32(smem);
    const int tid = threadIdx.x;
    const int w = tid >> 5;
    const int lane = tid & 31;
    const int wm = (w & 1) * 64;
    const int wn = (w >> 1) * 32;
    const int m0 = blockIdx.y * 128;
    const int n0 = blockIdx.x * 128;

    const int a_row = lane & 15;
    const int a_kh = (lane >> 4) & 1;
    const int b_n = (lane & 7) + ((lane >> 4) << 3);
    const int b_kh = (lane >> 3) & 1;

    float acc[4][4][4];
#pragma unroll
    for (int i = 0; i < 4; i++)
#pragma unroll
        for (int j = 0; j < 4; j++)
#pragma unroll
            for (int r = 0; r < 4; r++) acc[i][j][r] = 0.f;

    GEMM_MAINLOOP(Ahi, Alo, Bh, K)

    const int g = lane >> 2, c2 = lane & 3;
#pragma unroll
    for (int mt = 0; mt < 4; mt++) {
        const int row = m0 + wm + mt * 16 + g;
#pragma unroll
        for (int nt = 0; nt < 4; nt++) {
            const int col = n0 + wn + nt * 8 + c2 * 2;
            *(float2*)&C[(size_t)row * N + col] =
                make_float2(acc[mt][nt][0], acc[mt][nt][1]);
            *(float2*)&C[(size_t)(row + 8) * N + col] =
                make_float2(acc[mt][nt][2], acc[mt][nt][3]);
        }
    }
}

// ---------------- all-fp16 flash attention, single-pass S ----------------
// smem: Q(0, 18432) | KV buffers at 18432: Kh(0) Vh(9216), stride 18432
#define FKV  18432
#define FKV_STRIDE 18432
#define F_SMEM 55296

__global__ __launch_bounds__(256, 2) void flash_mma(
    const __half* __restrict__ Qh,
    const __half* __restrict__ Kh, const __half* __restrict__ Vh,
    __half* __restrict__ Ohf, __half* __restrict__ Olf) {
    extern __shared__ char smem[];
    const uint32_t sb = smem_u32(smem);
    const int tid = threadIdx.x;
    const int lane = tid & 31;
    const int w = tid >> 5;
    const int ib = gridDim.x - 1 - blockIdx.x;
    const int qh = blockIdx.y;
    const int kh = qh >> 2;
    const int qbase = ib * 128;

    // Q tile (fp16, 128 rows x 64 cols)
#pragma unroll
    for (int i = 0; i < 4; i++) {
        int idx = tid + i * 256;
        int r = idx >> 3, q = idx & 7;
        CP_ASYNC16(sb + r * 144 + q * 16,
                   Qh + (size_t)(qbase + r) * HID + qh * 64 + q * 8);
    }
    CP_COMMIT();

#pragma unroll
    for (int i = 0; i < 4; i++) {
        int idx = tid + i * 256;
        int sub = idx >> 9, r = (idx >> 3) & 63, q = idx & 7;
        const __half* base = sub ? Vh : Kh;
        CP_ASYNC16(sb + FKV + sub * 9216 + r * 144 + q * 16,
                   base + (size_t)r * KVD + kh * 64 + q * 8);
    }
    CP_COMMIT();

    const int a_row = lane & 15, a_kh = lane >> 4;
    const int b_n = (lane & 7) + ((lane >> 4) << 3), b_kh = (lane >> 3) & 1;
    const int v_k = (lane & 7) + ((lane >> 3) & 1) * 8, v_n = (lane >> 4) * 8;
    const int g = lane >> 2, tg = lane & 3;

    float o[8][4];
#pragma unroll
    for (int nt = 0; nt < 8; nt++)
#pragma unroll
        for (int r = 0; r < 4; r++) o[nt][r] = 0.f;
    float m0 = -1e30f, m1 = -1e30f, l0 = 0.f, l1 = 0.f;

    const int jbmax = 2 * ib + 1;
    for (int jb = 0; jb <= jbmax; jb++) {
        const uint32_t kvb = sb + FKV + (jb & 1) * FKV_STRIDE;
        __syncthreads();
        if (jb < jbmax) {
            const uint32_t nb = sb + FKV + ((jb + 1) & 1) * FKV_STRIDE;
#pragma unroll
            for (int i = 0; i < 4; i++) {
                int idx = tid + i * 256;
                int sub = idx >> 9, r = (idx >> 3) & 63, q = idx & 7;
                const __half* base = sub ? Vh : Kh;
                CP_ASYNC16(nb + sub * 9216 + r * 144 + q * 16,
                           base + (size_t)((jb + 1) * 64 + r) * KVD + kh * 64 + q * 8);
            }
            CP_COMMIT();
            CP_WAIT1();
        } else {
            CP_WAIT0();
        }
        __syncthreads();

        // S = Q K^T (single fp16 pass)
        float s[8][4];
#pragma unroll
        for (int nt = 0; nt < 8; nt++)
#pragma unroll
            for (int r = 0; r < 4; r++) s[nt][r] = 0.f;
#pragma unroll
        for (int kc = 0; kc < 4; kc++) {
            uint32_t ah[4];
            const uint32_t aoff = (w * 16 + a_row) * 144 + (kc * 16 + a_kh * 8) * 2;
            LDSM4(ah[0], ah[1], ah[2], ah[3], sb + aoff);
#pragma unroll
            for (int n2p = 0; n2p < 2; n2p++) {
                uint32_t bh[2][4];
#pragma unroll
                for (int j = 0; j < 2; j++) {
                    const int n2 = n2p * 2 + j;
                    const uint32_t boff = (n2 * 16 + b_n) * 144 + (kc * 16 + b_kh * 8) * 2;
                    LDSM4(bh[j][0], bh[j][1], bh[j][2], bh[j][3], kvb + boff);
                }
#pragma unroll
                for (int j = 0; j < 2; j++) {
                    const int n2 = n2p * 2 + j;
                    MMA16816F(s[n2 * 2 + 0], ah, bh[j][0], bh[j][1]);
                    MMA16816F(s[n2 * 2 + 1], ah, bh[j][2], bh[j][3]);
                }
            }
        }

        if (jb >= 2 * ib) {
            const int row0 = qbase + w * 16 + g;
            const int row1 = row0 + 8;
#pragma unroll
            for (int nt = 0; nt < 8; nt++) {
                const int col = jb * 64 + nt * 8 + tg * 2;
                if (col > row0) s[nt][0] = -1e30f;
                if (col + 1 > row0) s[nt][1] = -1e30f;
                if (col > row1) s[nt][2] = -1e30f;
                if (col + 1 > row1) s[nt][3] = -1e30f;
            }
        }

        float mx0 = -1e30f, mx1 = -1e30f;
#pragma unroll
        for (int nt = 0; nt < 8; nt++) {
            mx0 = fmaxf(mx0, fmaxf(s[nt][0], s[nt][1]));
            mx1 = fmaxf(mx1, fmaxf(s[nt][2], s[nt][3]));
        }
        mx0 = fmaxf(mx0, __shfl_xor_sync(0xffffffff, mx0, 1));
        mx0 = fmaxf(mx0, __shfl_xor_sync(0xffffffff, mx0, 2));
        mx1 = fmaxf(mx1, __shfl_xor_sync(0xffffffff, mx1, 1));
        mx1 = fmaxf(mx1, __shfl_xor_sync(0xffffffff, mx1, 2));
        const float mn0 = fmaxf(m0, mx0), mn1 = fmaxf(m1, mx1);
        const float al0 = __expf(m0 - mn0), al1 = __expf(m1 - mn1);
        m0 = mn0; m1 = mn1;

        float rs0 = 0.f, rs1 = 0.f;
#pragma unroll
        for (int nt = 0; nt < 8; nt++) {
            s[nt][0] = __expf(s[nt][0] - mn0);
            s[nt][1] = __expf(s[nt][1] - mn0);
            s[nt][2] = __expf(s[nt][2] - mn1);
            s[nt][3] = __expf(s[nt][3] - mn1);
            rs0 += s[nt][0] + s[nt][1];
            rs1 += s[nt][2] + s[nt][3];
            o[nt][0] *= al0; o[nt][1] *= al0;
            o[nt][2] *= al1; o[nt][3] *= al1;
        }
        rs0 += __shfl_xor_sync(0xffffffff, rs0, 1);
        rs0 += __shfl_xor_sync(0xffffffff, rs0, 2);
        rs1 += __shfl_xor_sync(0xffffffff, rs1, 1);
        rs1 += __shfl_xor_sync(0xffffffff, rs1, 2);
        l0 = l0 * al0 + rs0;
        l1 = l1 * al1 + rs1;

        // O += P @ V : fp16 2-pass
#pragma unroll
        for (int kc2 = 0; kc2 < 4; kc2++) {
            uint32_t aph[4], apl[4];
            pack_hl16(s[2 * kc2][0], s[2 * kc2][1], aph[0], apl[0]);
            pack_hl16(s[2 * kc2][2], s[2 * kc2][3], aph[1], apl[1]);
            pack_hl16(s[2 * kc2 + 1][0], s[2 * kc2 + 1][1], aph[2], apl[2]);
            pack_hl16(s[2 * kc2 + 1][2], s[2 * kc2 + 1][3], aph[3], apl[3]);
#pragma unroll
            for (int n2p = 0; n2p < 2; n2p++) {
                uint32_t vh[2][4];
#pragma unroll
                for (int j = 0; j < 2; j++) {
                    const int n2 = n2p * 2 + j;
                    const uint32_t voff = (kc2 * 16 + v_k) * 144 + (n2 * 16 + v_n) * 2;
                    LDSM4T(vh[j][0], vh[j][1], vh[j][2], vh[j][3], kvb + 9216 + voff);
                }
#pragma unroll
                for (int j = 0; j < 2; j++) {
                    const int n2 = n2p * 2 + j;
                    MMA16816F(o[n2 * 2 + 0], aph, vh[j][0], vh[j][1]);
                    MMA16816F(o[n2 * 2 + 1], aph, vh[j][2], vh[j][3]);
                }
#pragma unroll
                for (int j = 0; j < 2; j++) {
                    const int n2 = n2p * 2 + j;
                    MMA16816F(o[n2 * 2 + 0], apl, vh[j][0], vh[j][1]);
                    MMA16816F(o[n2 * 2 + 1], apl, vh[j][2], vh[j][3]);
                }
            }
        }
    }

    const float il0 = 1.0f / l0, il1 = 1.0f / l1;
    const int row0 = qbase + w * 16 + g;
#pragma unroll
    for (int nt = 0; nt < 8; nt++) {
        const int col = qh * 64 + nt * 8 + tg * 2;
        uint32_t h, l;
        pack_hl16(o[nt][0] * il0, o[nt][1] * il0, h, l);
        *(uint32_t*)&Ohf[(size_t)row0 * HID + col] = h;
        *(uint32_t*)&Olf[(size_t)row0 * HID + col] = l;
        pack_hl16(o[nt][2] * il1, o[nt][3] * il1, h, l);
        *(uint32_t*)&Ohf[(size_t)(row0 + 8) * HID + col] = h;
        *(uint32_t*)&Olf[(size_t)(row0 + 8) * HID + col] = l;
    }
}

// ---------------------------------------------------------------------------
extern "C" void kernel_launch(void* const* d_in, const int* in_sizes, int n_in,
                              void* d_out, int out_size) {
    const float* x        = (const float*)d_in[0];
    const float* q_proj   = (const float*)d_in[1];
    const float* k_proj   = (const float*)d_in[2];
    const float* v_proj   = (const float*)d_in[3];
    const float* o_proj   = (const float*)d_in[4];
    const float* inv_freq = (const float*)d_in[5];
    float* out = (float*)d_out;

    __half *Axh, *Axl, *Qh, *Ohf, *Olf, *Wh, *Kh, *Vh;
    float2* sc;
    cudaGetSymbolAddress((void**)&Axh, g_Axh);
    cudaGetSymbolAddress((void**)&Axl, g_Axl);
    cudaGetSymbolAddress((void**)&Qh, g_Qh);
    cudaGetSymbolAddress((void**)&Ohf, g_Ohf);
    cudaGetSymbolAddress((void**)&Olf, g_Olf);
    cudaGetSymbolAddress((void**)&Wh, g_Wh);
    cudaGetSymbolAddress((void**)&Kh, g_Kh);
    cudaGetSymbolAddress((void**)&Vh, g_Vh);
    cudaGetSymbolAddress((void**)&sc, g_sc);

    cudaFuncSetAttribute(gemm_qkv, cudaFuncAttributeMaxDynamicSharedMemorySize, G2_SMEM);
    cudaFuncSetAttribute(gemm_mma2, cudaFuncAttributeMaxDynamicSharedMemorySize, G2_SMEM);
    cudaFuncSetAttribute(flash_mma, cudaFuncAttributeMaxDynamicSharedMemorySize, F_SMEM);

    const int convBlocks = (SEQ * HID / 4) / 256;

    convert_hl16<<<convBlocks, 256>>>(x, Axh, Axl);
    transpose_all16<<<dim3(160, HID / 32), 256>>>(q_proj, k_proj, v_proj, o_proj, Wh);
    sc_init<<<SEQ * 32 / 256, 256>>>(inv_freq, sc);

    // fused QKV projection + rope + fp16 convert (no fp32 intermediate)
    gemm_qkv<<<dim3(QKVN / 128, SEQ / 128), 256, G2_SMEM>>>(Axh, Axl, Wh, Qh, Kh, Vh, sc);

    // all-fp16 flash attention (single-pass S, 2-pass PV)
    flash_mma<<<dim3(SEQ / 128, NQH), 256, F_SMEM>>>(Qh, Kh, Vh, Ohf, Olf);

    // out = O @ o_proj (fp16 2-pass)
    gemm_mma2<<<dim3(HID / 128, SEQ / 128), 256, G2_SMEM>>>(Ohf, Olf, Wh + (size_t)QKVN * HID,
                                                            out, SEQ, HID, HID);
}

// round 15
// speedup vs baseline: 1.2953x; 1.2079x over previous
#include <cuda_runtime.h>
#include <cuda_fp16.h>
#include <math.h>
#include <cstdint>

#define SEQ 2048
#define HID 2048
#define KVD 512
#define QKVN 3072
#define WROWS 5120
#define NQH 32
#define NKH 8

// ---------------- scratch (no allocations allowed) ----------------
__device__ __half g_Axh[SEQ * HID];          // x fp16 hi
__device__ __half g_Axl[SEQ * HID];          // x fp16 lo
__device__ __half g_Qh[SEQ * HID];           // Q fp16 (post-rope, scaled)
__device__ __half g_Oh[SEQ * HID];           // attention output fp16
__device__ __half g_Wh[WROWS * HID];         // transposed q|k|v|o weights, fp16
__device__ __half g_Kh[SEQ * KVD];           // K fp16 (post-rope)
__device__ __half g_Vh[SEQ * KVD];           // V fp16
__device__ float2 g_sc[SEQ * 32];            // sincos LUT

// ---------------- helpers ----------------
__device__ __forceinline__ uint32_t smem_u32(const void* p) {
    uint32_t a;
    asm("{ .reg .u64 t; cvta.to.shared.u64 t, %1; cvt.u32.u64 %0, t; }" : "=r"(a) : "l"(p));
    return a;
}

#define LDSM4(r0, r1, r2, r3, addr) \
    asm volatile("ldmatrix.sync.aligned.m8n8.x4.shared.b16 {%0,%1,%2,%3}, [%4];" \
        : "=r"(r0), "=r"(r1), "=r"(r2), "=r"(r3) : "r"(addr))

#define LDSM4T(r0, r1, r2, r3, addr) \
    asm volatile("ldmatrix.sync.aligned.m8n8.x4.trans.shared.b16 {%0,%1,%2,%3}, [%4];" \
        : "=r"(r0), "=r"(r1), "=r"(r2), "=r"(r3) : "r"(addr))

#define MMA16816F(d, a, b0, b1) \
    asm volatile("mma.sync.aligned.m16n8k16.row.col.f32.f16.f16.f32 " \
        "{%0,%1,%2,%3},{%4,%5,%6,%7},{%8,%9},{%0,%1,%2,%3};" \
        : "+f"((d)[0]), "+f"((d)[1]), "+f"((d)[2]), "+f"((d)[3]) \
        : "r"((a)[0]), "r"((a)[1]), "r"((a)[2]), "r"((a)[3]), "r"(b0), "r"(b1))

#define CP_ASYNC16(dst, src) \
    asm volatile("cp.async.cg.shared.global [%0], [%1], 16;" :: "r"(dst), "l"(src))
#define CP_COMMIT() asm volatile("cp.async.commit_group;" ::: "memory")
#define CP_WAIT0()  asm volatile("cp.async.wait_group 0;" ::: "memory")
#define CP_WAIT1()  asm volatile("cp.async.wait_group 1;" ::: "memory")

// ---------------- elementwise kernels ----------------
__device__ __forceinline__ void pack_hl16(float p0, float p1, uint32_t& hi, uint32_t& lo) {
    __half2 h = __floats2half2_rn(p0, p1);
    hi = *reinterpret_cast<uint32_t*>(&h);
    __half2 l = __floats2half2_rn(p0 - __half2float(__low2half(h)),
                                  p1 - __half2float(__high2half(h)));
    lo = *reinterpret_cast<uint32_t*>(&l);
}

__global__ __launch_bounds__(256) void convert_hl16(const float* __restrict__ X,
                                                    __half* __restrict__ hi,
                                                    __half* __restrict__ lo) {
    int i = blockIdx.x * 256 + threadIdx.x;
    float4 v = *(const float4*)(X + (size_t)i * 4);
    uint32_t h0, l0, h1, l1;
    pack_hl16(v.x, v.y, h0, l0);
    pack_hl16(v.z, v.w, h1, l1);
    *(uint2*)(hi + (size_t)i * 4) = make_uint2(h0, h1);
    *(uint2*)(lo + (size_t)i * 4) = make_uint2(l0, l1);
}

__global__ __launch_bounds__(256) void transpose_all16(const float* __restrict__ Wq,
                                                       const float* __restrict__ Wk,
                                                       const float* __restrict__ Wv,
                                                       const float* __restrict__ Wo,
                                                       __half* __restrict__ toh) {
    __shared__ float t[32][33];
    int bx = blockIdx.x;
    const float* W;
    int N, nblk, dstoff;
    if (bx < 64)       { W = Wq; N = HID; nblk = bx;      dstoff = 0; }
    else if (bx < 80)  { W = Wk; N = KVD; nblk = bx - 64; dstoff = HID; }
    else if (bx < 96)  { W = Wv; N = KVD; nblk = bx - 80; dstoff = HID + KVD; }
    else               { W = Wo; N = HID; nblk = bx - 96; dstoff = QKVN; }
    int tx = threadIdx.x & 31, ty = threadIdx.x >> 5;
    int k0 = blockIdx.y * 32, n0 = nblk * 32;
#pragma unroll
    for (int i = 0; i < 4; i++)
        t[ty + i * 8][tx] = W[(size_t)(k0 + ty + i * 8) * N + n0 + tx];
    __syncthreads();
#pragma unroll
    for (int i = 0; i < 4; i++) {
        float v = t[tx][ty + i * 8];
        toh[(size_t)(dstoff + n0 + ty + i * 8) * HID + k0 + tx] = __float2half_rn(v);
    }
}

__global__ __launch_bounds__(256) void sc_init(const float* __restrict__ inv_freq,
                                               float2* __restrict__ sc) {
    int i = blockIdx.x * 256 + threadIdx.x;
    int s = i >> 5, j = i & 31;
    float angle = (float)s * inv_freq[j];
    sc[i] = make_float2(sinf(angle), cosf(angle));
}

// ---------------- GEMM mainloop pieces ----------------
#define TILE_B 10240
#define BUF2_B 30720
#define G2_SMEM (2 * BUF2_B)
#define BUF1_B 20480
#define G1_SMEM (2 * BUF1_B)
#define SPAD 132

__device__ __forceinline__ void tile_async(uint32_t dst, const void* src_,
                                           int ldk, int tid) {
    const __half* src = (const __half*)src_;
#pragma unroll
    for (int t = 0; t < 2; t++) {
        int i = tid + t * 256;
        int r = i >> 2, q = i & 3;
        CP_ASYNC16(dst + r * 80 + q * 16, src + (size_t)r * ldk + q * 8);
    }
}

// 2-pass mainloop (A hi/lo, B hi)
#define GEMM_MAINLOOP2(Ahi, Alo, Bh, K)                                             \
    const int NC = (K) >> 5;                                                        \
    {                                                                               \
        const size_t ak = (size_t)m0 * (K);                                         \
        const size_t bk = (size_t)n0 * (K);                                         \
        tile_async(sb,              (Ahi) + ak, (K), tid);                          \
        tile_async(sb + TILE_B,     (Alo) + ak, (K), tid);                          \
        tile_async(sb + 2 * TILE_B, (Bh) + bk, (K), tid);                           \
        CP_COMMIT();                                                                \
    }                                                                               \
    for (int c = 0; c < NC; c++) {                                                  \
        CP_WAIT0();                                                                 \
        __syncthreads();                                                            \
        if (c + 1 < NC) {                                                           \
            const uint32_t nb = sb + ((c + 1) & 1) * BUF2_B;                        \
            const size_t ak = (size_t)m0 * (K) + (size_t)(c + 1) * 32;              \
            const size_t bk = (size_t)n0 * (K) + (size_t)(c + 1) * 32;              \
            tile_async(nb,              (Ahi) + ak, (K), tid);                      \
            tile_async(nb + TILE_B,     (Alo) + ak, (K), tid);                      \
            tile_async(nb + 2 * TILE_B, (Bh) + bk, (K), tid);                       \
            CP_COMMIT();                                                            \
        }                                                                           \
        const uint32_t base = sb + (c & 1) * BUF2_B;                                \
        _Pragma("unroll")                                                           \
        for (int ks = 0; ks < 32; ks += 16) {                                       \
            uint32_t ah[4][4], al[4][4], bh[2][4];                                  \
            const uint32_t aoff = (uint32_t)((wm + a_row) * 80 + (ks + a_kh * 8) * 2); \
            const uint32_t boff = (uint32_t)((wn + b_n) * 80 + (ks + b_kh * 8) * 2);   \
            _Pragma("unroll")                                                       \
            for (int mt = 0; mt < 4; mt++) {                                        \
                LDSM4(ah[mt][0], ah[mt][1], ah[mt][2], ah[mt][3],                   \
                      base + aoff + mt * 16 * 80);                                  \
                LDSM4(al[mt][0], al[mt][1], al[mt][2], al[mt][3],                   \
                      base + TILE_B + aoff + mt * 16 * 80);                         \
            }                                                                       \
            _Pragma("unroll")                                                       \
            for (int np = 0; np < 2; np++)                                          \
                LDSM4(bh[np][0], bh[np][1], bh[np][2], bh[np][3],                   \
                      base + 2 * TILE_B + boff + np * 16 * 80);                     \
            _Pragma("unroll")                                                       \
            for (int mt = 0; mt < 4; mt++)                                          \
                _Pragma("unroll")                                                   \
                for (int np = 0; np < 2; np++) {                                    \
                    MMA16816F(acc[mt][np * 2 + 0], ah[mt], bh[np][0], bh[np][1]);   \
                    MMA16816F(acc[mt][np * 2 + 1], ah[mt], bh[np][2], bh[np][3]);   \
                }                                                                   \
            _Pragma("unroll")                                                       \
            for (int mt = 0; mt < 4; mt++)                                          \
                _Pragma("unroll")                                                   \
                for (int np = 0; np < 2; np++) {                                    \
                    MMA16816F(acc[mt][np * 2 + 0], al[mt], bh[np][0], bh[np][1]);   \
                    MMA16816F(acc[mt][np * 2 + 1], al[mt], bh[np][2], bh[np][3]);   \
                }                                                                   \
        }                                                                           \
    }

// ---------------- QKV GEMM with fused rope/convert epilogue (2-pass A) ----------------
__global__ __launch_bounds__(256, 2) void gemm_qkv(
    const __half* __restrict__ Ahi, const __half* __restrict__ Alo,
    const __half* __restrict__ Bh,
    __half* __restrict__ Qh, __half* __restrict__ Kh, __half* __restrict__ Vh,
    const float2* __restrict__ sc) {
    extern __shared__ char smem[];
    const uint32_t sb = smem_u32(smem);
    const int tid = threadIdx.x;
    const int w = tid >> 5;
    const int lane = tid & 31;
    const int wm = (w & 1) * 64;
    const int wn = (w >> 1) * 32;
    const int m0 = blockIdx.y * 128;
    const int n0 = blockIdx.x * 128;

    const int a_row = lane & 15;
    const int a_kh = (lane >> 4) & 1;
    const int b_n = (lane & 7) + ((lane >> 4) << 3);
    const int b_kh = (lane >> 3) & 1;

    float acc[4][4][4];
#pragma unroll
    for (int i = 0; i < 4; i++)
#pragma unroll
        for (int j = 0; j < 4; j++)
#pragma unroll
            for (int r = 0; r < 4; r++) acc[i][j][r] = 0.f;

    GEMM_MAINLOOP2(Ahi, Alo, Bh, HID)

    const int g = lane >> 2, c2 = lane & 3;

    if (n0 >= HID + KVD) {
        const int vcol0 = n0 - (HID + KVD);
#pragma unroll
        for (int mt = 0; mt < 4; mt++) {
            const int row = m0 + wm + mt * 16 + g;
#pragma unroll
            for (int nt = 0; nt < 4; nt++) {
                const int col = vcol0 + wn + nt * 8 + c2 * 2;
                __half2 v0 = __floats2half2_rn(acc[mt][nt][0], acc[mt][nt][1]);
                __half2 v1 = __floats2half2_rn(acc[mt][nt][2], acc[mt][nt][3]);
                *(uint32_t*)&Vh[(size_t)row * KVD + col] = *reinterpret_cast<uint32_t*>(&v0);
                *(uint32_t*)&Vh[(size_t)(row + 8) * KVD + col] = *reinterpret_cast<uint32_t*>(&v1);
            }
        }
        return;
    }

    const bool isQ = (n0 < HID);
    const float scale = isQ ? 0.125f : 1.0f;
    float* st = (float*)smem;

#pragma unroll
    for (int h = 0; h < 2; h++) {
        __syncthreads();
#pragma unroll
        for (int mt2 = 0; mt2 < 2; mt2++) {
            const int mt = 2 * h + mt2;
            const int sr = (w & 1) * 32 + mt2 * 16 + g;
#pragma unroll
            for (int nt = 0; nt < 4; nt++) {
                const int col = wn + nt * 8 + c2 * 2;
                st[sr * SPAD + col] = acc[mt][nt][0];
                st[sr * SPAD + col + 1] = acc[mt][nt][1];
                st[(sr + 8) * SPAD + col] = acc[mt][nt][2];
                st[(sr + 8) * SPAD + col + 1] = acc[mt][nt][3];
            }
        }
        __syncthreads();
#pragma unroll
        for (int i = 0; i < 16; i++) {
            const int idx = tid + i * 256;
            const int sr = idx >> 6;
            const int col = (idx & 63) * 2;
            const int br = (sr < 32) ? h * 32 + sr : 64 + h * 32 + (sr - 32);
            const int s = m0 + br;
            const int hl = col & 63;
            const int j = hl & 31;
            const float2 sc0 = sc[s * 32 + j];
            const float2 sc1 = sc[s * 32 + j + 1];
            const float v0 = st[sr * SPAD + col], v1 = st[sr * SPAD + col + 1];
            float r0, r1;
            if (hl < 32) {
                const float b0 = st[sr * SPAD + col + 32], b1 = st[sr * SPAD + col + 33];
                r0 = (v0 * sc0.y + b0 * sc0.x) * scale;
                r1 = (v1 * sc1.y + b1 * sc1.x) * scale;
            } else {
                const float a0 = st[sr * SPAD + col - 32], a1 = st[sr * SPAD + col - 31];
                r0 = (a0 * sc0.x - v0 * sc0.y) * scale;
                r1 = (a1 * sc1.x - v1 * sc1.y) * scale;
            }
            __half2 v = __floats2half2_rn(r0, r1);
            if (isQ) {
                *(uint32_t*)&Qh[(size_t)s * HID + n0 + col] = *reinterpret_cast<uint32_t*>(&v);
            } else {
                *(uint32_t*)&Kh[(size_t)s * KVD + (n0 - HID) + col] =
                    *reinterpret_cast<uint32_t*>(&v);
            }
        }
    }
}

// ---------------- single-pass fp16 GEMM (O projection) ----------------
__global__ __launch_bounds__(256, 2) void gemm_mma1(
    const __half* __restrict__ Ah, const __half* __restrict__ Bh,
    float* __restrict__ C, int M, int N, int K) {
    extern __shared__ char smem[];
    const uint32_t sb = smem_u32(smem);
    const int tid = threadIdx.x;
    const int w = tid >> 5;
    const int lane = tid & 31;
    const int wm = (w & 1) * 64;
    const int wn = (w >> 1) * 32;
    const int m0 = blockIdx.y * 128;
    const int n0 = blockIdx.x * 128;

    const int a_row = lane & 15;
    const int a_kh = (lane >> 4) & 1;
    const int b_n = (lane & 7) + ((lane >> 4) << 3);
    const int b_kh = (lane >> 3) & 1;

    float acc[4][4][4];
#pragma unroll
    for (int i = 0; i < 4; i++)
#pragma unroll
        for (int j = 0; j < 4; j++)
#pragma unroll
            for (int r = 0; r < 4; r++) acc[i][j][r] = 0.f;

    const int NC = K >> 5;
    {
        tile_async(sb,          Ah + (size_t)m0 * K, K, tid);
        tile_async(sb + TILE_B, Bh + (size_t)n0 * K, K, tid);
        CP_COMMIT();
    }
    for (int c = 0; c < NC; c++) {
        CP_WAIT0();
        __syncthreads();
        if (c + 1 < NC) {
            const uint32_t nb = sb + ((c + 1) & 1) * BUF1_B;
            tile_async(nb,          Ah + (size_t)m0 * K + (size_t)(c + 1) * 32, K, tid);
            tile_async(nb + TILE_B, Bh + (size_t)n0 * K + (size_t)(c + 1) * 32, K, tid);
            CP_COMMIT();
        }
        const uint32_t base = sb + (c & 1) * BUF1_B;
#pragma unroll
        for (int ks = 0; ks < 32; ks += 16) {
            uint32_t ah[4][4], bh[2][4];
            const uint32_t aoff = (uint32_t)((wm + a_row) * 80 + (ks + a_kh * 8) * 2);
            const uint32_t boff = (uint32_t)((wn + b_n) * 80 + (ks + b_kh * 8) * 2);
#pragma unroll
            for (int mt = 0; mt < 4; mt++)
                LDSM4(ah[mt][0], ah[mt][1], ah[mt][2], ah[mt][3],
                      base + aoff + mt * 16 * 80);
#pragma unroll
            for (int np = 0; np < 2; np++)
                LDSM4(bh[np][0], bh[np][1], bh[np][2], bh[np][3],
                      base + TILE_B + boff + np * 16 * 80);
#pragma unroll
            for (int mt = 0; mt < 4; mt++)
#pragma unroll
                for (int np = 0; np < 2; np++) {
                    MMA16816F(acc[mt][np * 2 + 0], ah[mt], bh[np][0], bh[np][1]);
                    MMA16816F(acc[mt][np * 2 + 1], ah[mt], bh[np][2], bh[np][3]);
                }
        }
    }

    const int g = lane >> 2, c2 = lane & 3;
#pragma unroll
    for (int mt = 0; mt < 4; mt++) {
        const int row = m0 + wm + mt * 16 + g;
#pragma unroll
        for (int nt = 0; nt < 4; nt++) {
            const int col = n0 + wn + nt * 8 + c2 * 2;
            *(float2*)&C[(size_t)row * N + col] =
                make_float2(acc[mt][nt][0], acc[mt][nt][1]);
            *(float2*)&C[(size_t)(row + 8) * N + col] =
                make_float2(acc[mt][nt][2], acc[mt][nt][3]);
        }
    }
}

// ---------------- all-fp16 flash attention, single-pass S and PV ----------------
#define FKV  18432
#define FKV_STRIDE 18432
#define F_SMEM 55296

__global__ __launch_bounds__(256, 2) void flash_mma(
    const __half* __restrict__ Qh,
    const __half* __restrict__ Kh, const __half* __restrict__ Vh,
    __half* __restrict__ Oh) {
    extern __shared__ char smem[];
    const uint32_t sb = smem_u32(smem);
    const int tid = threadIdx.x;
    const int lane = tid & 31;
    const int w = tid >> 5;
    const int ib = gridDim.x - 1 - blockIdx.x;
    const int qh = blockIdx.y;
    const int kh = qh >> 2;
    const int qbase = ib * 128;

#pragma unroll
    for (int i = 0; i < 4; i++) {
        int idx = tid + i * 256;
        int r = idx >> 3, q = idx & 7;
        CP_ASYNC16(sb + r * 144 + q * 16,
                   Qh + (size_t)(qbase + r) * HID + qh * 64 + q * 8);
    }
    CP_COMMIT();

#pragma unroll
    for (int i = 0; i < 4; i++) {
        int idx = tid + i * 256;
        int sub = idx >> 9, r = (idx >> 3) & 63, q = idx & 7;
        const __half* base = sub ? Vh : Kh;
        CP_ASYNC16(sb + FKV + sub * 9216 + r * 144 + q * 16,
                   base + (size_t)r * KVD + kh * 64 + q * 8);
    }
    CP_COMMIT();

    const int a_row = lane & 15, a_kh = lane >> 4;
    const int b_n = (lane & 7) + ((lane >> 4) << 3), b_kh = (lane >> 3) & 1;
    const int v_k = (lane & 7) + ((lane >> 3) & 1) * 8, v_n = (lane >> 4) * 8;
    const int g = lane >> 2, tg = lane & 3;

    float o[8][4];
#pragma unroll
    for (int nt = 0; nt < 8; nt++)
#pragma unroll
        for (int r = 0; r < 4; r++) o[nt][r] = 0.f;
    float m0 = -1e30f, m1 = -1e30f, l0 = 0.f, l1 = 0.f;

    const int jbmax = 2 * ib + 1;
    for (int jb = 0; jb <= jbmax; jb++) {
        const uint32_t kvb = sb + FKV + (jb & 1) * FKV_STRIDE;
        __syncthreads();
        if (jb < jbmax) {
            const uint32_t nb = sb + FKV + ((jb + 1) & 1) * FKV_STRIDE;
#pragma unroll
            for (int i = 0; i < 4; i++) {
                int idx = tid + i * 256;
                int sub = idx >> 9, r = (idx >> 3) & 63, q = idx & 7;
                const __half* base = sub ? Vh : Kh;
                CP_ASYNC16(nb + sub * 9216 + r * 144 + q * 16,
                           base + (size_t)((jb + 1) * 64 + r) * KVD + kh * 64 + q * 8);
            }
            CP_COMMIT();
            CP_WAIT1();
        } else {
            CP_WAIT0();
        }
        __syncthreads();

        // S = Q K^T (single fp16 pass)
        float s[8][4];
#pragma unroll
        for (int nt = 0; nt < 8; nt++)
#pragma unroll
            for (int r = 0; r < 4; r++) s[nt][r] = 0.f;
#pragma unroll
        for (int kc = 0; kc < 4; kc++) {
            uint32_t ah[4];
            const uint32_t aoff = (w * 16 + a_row) * 144 + (kc * 16 + a_kh * 8) * 2;
            LDSM4(ah[0], ah[1], ah[2], ah[3], sb + aoff);
#pragma unroll
            for (int n2p = 0; n2p < 2; n2p++) {
                uint32_t bh[2][4];
#pragma unroll
                for (int j = 0; j < 2; j++) {
                    const int n2 = n2p * 2 + j;
                    const uint32_t boff = (n2 * 16 + b_n) * 144 + (kc * 16 + b_kh * 8) * 2;
                    LDSM4(bh[j][0], bh[j][1], bh[j][2], bh[j][3], kvb + boff);
                }
#pragma unroll
                for (int j = 0; j < 2; j++) {
                    const int n2 = n2p * 2 + j;
                    MMA16816F(s[n2 * 2 + 0], ah, bh[j][0], bh[j][1]);
                    MMA16816F(s[n2 * 2 + 1], ah, bh[j][2], bh[j][3]);
                }
            }
        }

        if (jb >= 2 * ib) {
            const int row0 = qbase + w * 16 + g;
            const int row1 = row0 + 8;
#pragma unroll
            for (int nt = 0; nt < 8; nt++) {
                const int col = jb * 64 + nt * 8 + tg * 2;
                if (col > row0) s[nt][0] = -1e30f;
                if (col + 1 > row0) s[nt][1] = -1e30f;
                if (col > row1) s[nt][2] = -1e30f;
                if (col + 1 > row1) s[nt][3] = -1e30f;
            }
        }

        float mx0 = -1e30f, mx1 = -1e30f;
#pragma unroll
        for (int nt = 0; nt < 8; nt++) {
            mx0 = fmaxf(mx0, fmaxf(s[nt][0], s[nt][1]));
            mx1 = fmaxf(mx1, fmaxf(s[nt][2], s[nt][3]));
        }
        mx0 = fmaxf(mx0, __shfl_xor_sync(0xffffffff, mx0, 1));
        mx0 = fmaxf(mx0, __shfl_xor_sync(0xffffffff, mx0, 2));
        mx1 = fmaxf(mx1, __shfl_xor_sync(0xffffffff, mx1, 1));
        mx1 = fmaxf(mx1, __shfl_xor_sync(0xffffffff, mx1, 2));
        const float mn0 = fmaxf(m0, mx0), mn1 = fmaxf(m1, mx1);
        const float al0 = __expf(m0 - mn0), al1 = __expf(m1 - mn1);
        m0 = mn0; m1 = mn1;

        float rs0 = 0.f, rs1 = 0.f;
#pragma unroll
        for (int nt = 0; nt < 8; nt++) {
            s[nt][0] = __expf(s[nt][0] - mn0);
            s[nt][1] = __expf(s[nt][1] - mn0);
            s[nt][2] = __expf(s[nt][2] - mn1);
            s[nt][3] = __expf(s[nt][3] - mn1);
            rs0 += s[nt][0] + s[nt][1];
            rs1 += s[nt][2] + s[nt][3];
            o[nt][0] *= al0; o[nt][1] *= al0;
            o[nt][2] *= al1; o[nt][3] *= al1;
        }
        rs0 += __shfl_xor_sync(0xffffffff, rs0, 1);
        rs0 += __shfl_xor_sync(0xffffffff, rs0, 2);
        rs1 += __shfl_xor_sync(0xffffffff, rs1, 1);
        rs1 += __shfl_xor_sync(0xffffffff, rs1, 2);
        l0 = l0 * al0 + rs0;
        l1 = l1 * al1 + rs1;

        // O += P @ V : single fp16 pass
#pragma unroll
        for (int kc2 = 0; kc2 < 4; kc2++) {
            uint32_t aph[4];
            __half2 p0 = __floats2half2_rn(s[2 * kc2][0], s[2 * kc2][1]);
            __half2 p1 = __floats2half2_rn(s[2 * kc2][2], s[2 * kc2][3]);
            __half2 p2 = __floats2half2_rn(s[2 * kc2 + 1][0], s[2 * kc2 + 1][1]);
            __half2 p3 = __floats2half2_rn(s[2 * kc2 + 1][2], s[2 * kc2 + 1][3]);
            aph[0] = *reinterpret_cast<uint32_t*>(&p0);
            aph[1] = *reinterpret_cast<uint32_t*>(&p1);
            aph[2] = *reinterpret_cast<uint32_t*>(&p2);
            aph[3] = *reinterpret_cast<uint32_t*>(&p3);
#pragma unroll
            for (int n2p = 0; n2p < 2; n2p++) {
                uint32_t vh[2][4];
#pragma unroll
                for (int j = 0; j < 2; j++) {
                    const int n2 = n2p * 2 + j;
                    const uint32_t voff = (kc2 * 16 + v_k) * 144 + (n2 * 16 + v_n) * 2;
                    LDSM4T(vh[j][0], vh[j][1], vh[j][2], vh[j][3], kvb + 9216 + voff);
                }
#pragma unroll
                for (int j = 0; j < 2; j++) {
                    const int n2 = n2p * 2 + j;
                    MMA16816F(o[n2 * 2 + 0], aph, vh[j][0], vh[j][1]);
                    MMA16816F(o[n2 * 2 + 1], aph, vh[j][2], vh[j][3]);
                }
            }
        }
    }

    const float il0 = 1.0f / l0, il1 = 1.0f / l1;
    const int row0 = qbase + w * 16 + g;
#pragma unroll
    for (int nt = 0; nt < 8; nt++) {
        const int col = qh * 64 + nt * 8 + tg * 2;
        __half2 v0 = __floats2half2_rn(o[nt][0] * il0, o[nt][1] * il0);
        __half2 v1 = __floats2half2_rn(o[nt][2] * il1, o[nt][3] * il1);
        *(uint32_t*)&Oh[(size_t)row0 * HID + col] = *reinterpret_cast<uint32_t*>(&v0);
        *(uint32_t*)&Oh[(size_t)(row0 + 8) * HID + col] = *reinterpret_cast<uint32_t*>(&v1);
    }
}

// ---------------------------------------------------------------------------
extern "C" void kernel_launch(void* const* d_in, const int* in_sizes, int n_in,
                              void* d_out, int out_size) {
    const float* x        = (const float*)d_in[0];
    const float* q_proj   = (const float*)d_in[1];
    const float* k_proj   = (const float*)d_in[2];
    const float* v_proj   = (const float*)d_in[3];
    const float* o_proj   = (const float*)d_in[4];
    const float* inv_freq = (const float*)d_in[5];
    float* out = (float*)d_out;

    __half *Axh, *Axl, *Qh, *Oh, *Wh, *Kh, *Vh;
    float2* sc;
    cudaGetSymbolAddress((void**)&Axh, g_Axh);
    cudaGetSymbolAddress((void**)&Axl, g_Axl);
    cudaGetSymbolAddress((void**)&Qh, g_Qh);
    cudaGetSymbolAddress((void**)&Oh, g_Oh);
    cudaGetSymbolAddress((void**)&Wh, g_Wh);
    cudaGetSymbolAddress((void**)&Kh, g_Kh);
    cudaGetSymbolAddress((void**)&Vh, g_Vh);
    cudaGetSymbolAddress((void**)&sc, g_sc);

    cudaFuncSetAttribute(gemm_qkv, cudaFuncAttributeMaxDynamicSharedMemorySize, G2_SMEM);
    cudaFuncSetAttribute(gemm_mma1, cudaFuncAttributeMaxDynamicSharedMemorySize, G1_SMEM);
    cudaFuncSetAttribute(flash_mma, cudaFuncAttributeMaxDynamicSharedMemorySize, F_SMEM);

    const int convBlocks = (SEQ * HID / 4) / 256;

    convert_hl16<<<convBlocks, 256>>>(x, Axh, Axl);
    transpose_all16<<<dim3(160, HID / 32), 256>>>(q_proj, k_proj, v_proj, o_proj, Wh);
    sc_init<<<SEQ * 32 / 256, 256>>>(inv_freq, sc);

    // fused QKV projection + rope + fp16 convert (x 2-pass)
    gemm_qkv<<<dim3(QKVN / 128, SEQ / 128), 256, G2_SMEM>>>(Axh, Axl, Wh, Qh, Kh, Vh, sc);

    // all-fp16 flash attention (single-pass S, single-pass PV)
    flash_mma<<<dim3(SEQ / 128, NQH), 256, F_SMEM>>>(Qh, Kh, Vh, Oh);

    // out = O @ o_proj (single-pass fp16)
    gemm_mma1<<<dim3(HID / 128, SEQ / 128), 256, G1_SMEM>>>(Oh, Wh + (size_t)QKVN * HID,
                                                            out, SEQ, HID, HID);
}

// round 16
// speedup vs baseline: 1.6225x; 1.2526x over previous
#include <cuda_runtime.h>
#include <cuda_fp16.h>
#include <math.h>
#include <cstdint>

#define SEQ 2048
#define HID 2048
#define KVD 512
#define QKVN 3072
#define WROWS 5120
#define NQH 32
#define NKH 8

// ---------------- scratch (no allocations allowed) ----------------
__device__ __half g_Axh[SEQ * HID];          // x fp16
__device__ __half g_Qh[SEQ * HID];           // Q fp16 (post-rope, scaled)
__device__ __half g_Oh[SEQ * HID];           // attention output fp16
__device__ __half g_Wh[WROWS * HID];         // transposed q|k|v|o weights, fp16
__device__ __half g_Kh[SEQ * KVD];           // K fp16 (post-rope)
__device__ __half g_Vh[SEQ * KVD];           // V fp16
__device__ float2 g_sc[SEQ * 32];            // sincos LUT

// ---------------- helpers ----------------
__device__ __forceinline__ uint32_t smem_u32(const void* p) {
    uint32_t a;
    asm("{ .reg .u64 t; cvta.to.shared.u64 t, %1; cvt.u32.u64 %0, t; }" : "=r"(a) : "l"(p));
    return a;
}

#define LDSM4(r0, r1, r2, r3, addr) \
    asm volatile("ldmatrix.sync.aligned.m8n8.x4.shared.b16 {%0,%1,%2,%3}, [%4];" \
        : "=r"(r0), "=r"(r1), "=r"(r2), "=r"(r3) : "r"(addr))

#define LDSM4T(r0, r1, r2, r3, addr) \
    asm volatile("ldmatrix.sync.aligned.m8n8.x4.trans.shared.b16 {%0,%1,%2,%3}, [%4];" \
        : "=r"(r0), "=r"(r1), "=r"(r2), "=r"(r3) : "r"(addr))

#define MMA16816F(d, a, b0, b1) \
    asm volatile("mma.sync.aligned.m16n8k16.row.col.f32.f16.f16.f32 " \
        "{%0,%1,%2,%3},{%4,%5,%6,%7},{%8,%9},{%0,%1,%2,%3};" \
        : "+f"((d)[0]), "+f"((d)[1]), "+f"((d)[2]), "+f"((d)[3]) \
        : "r"((a)[0]), "r"((a)[1]), "r"((a)[2]), "r"((a)[3]), "r"(b0), "r"(b1))

#define CP_ASYNC16(dst, src) \
    asm volatile("cp.async.cg.shared.global [%0], [%1], 16;" :: "r"(dst), "l"(src))
#define CP_COMMIT() asm volatile("cp.async.commit_group;" ::: "memory")
#define CP_WAIT0()  asm volatile("cp.async.wait_group 0;" ::: "memory")
#define CP_WAIT1()  asm volatile("cp.async.wait_group 1;" ::: "memory")

// ---------------- elementwise kernels ----------------
__global__ __launch_bounds__(256) void convert_h16(const float* __restrict__ X,
                                                   __half* __restrict__ h) {
    int i = blockIdx.x * 256 + threadIdx.x;
    float4 v = *(const float4*)(X + (size_t)i * 4);
    __half2 a = __floats2half2_rn(v.x, v.y);
    __half2 b = __floats2half2_rn(v.z, v.w);
    *(uint2*)(h + (size_t)i * 4) =
        make_uint2(*reinterpret_cast<uint32_t*>(&a), *reinterpret_cast<uint32_t*>(&b));
}

__global__ __launch_bounds__(256) void transpose_all16(const float* __restrict__ Wq,
                                                       const float* __restrict__ Wk,
                                                       const float* __restrict__ Wv,
                                                       const float* __restrict__ Wo,
                                                       __half* __restrict__ toh) {
    __shared__ float t[32][33];
    int bx = blockIdx.x;
    const float* W;
    int N, nblk, dstoff;
    if (bx < 64)       { W = Wq; N = HID; nblk = bx;      dstoff = 0; }
    else if (bx < 80)  { W = Wk; N = KVD; nblk = bx - 64; dstoff = HID; }
    else if (bx < 96)  { W = Wv; N = KVD; nblk = bx - 80; dstoff = HID + KVD; }
    else               { W = Wo; N = HID; nblk = bx - 96; dstoff = QKVN; }
    int tx = threadIdx.x & 31, ty = threadIdx.x >> 5;
    int k0 = blockIdx.y * 32, n0 = nblk * 32;
#pragma unroll
    for (int i = 0; i < 4; i++)
        t[ty + i * 8][tx] = W[(size_t)(k0 + ty + i * 8) * N + n0 + tx];
    __syncthreads();
#pragma unroll
    for (int i = 0; i < 4; i++) {
        float v = t[tx][ty + i * 8];
        toh[(size_t)(dstoff + n0 + ty + i * 8) * HID + k0 + tx] = __float2half_rn(v);
    }
}

__global__ __launch_bounds__(256) void sc_init(const float* __restrict__ inv_freq,
                                               float2* __restrict__ sc) {
    int i = blockIdx.x * 256 + threadIdx.x;
    int s = i >> 5, j = i & 31;
    float angle = (float)s * inv_freq[j];
    sc[i] = make_float2(sinf(angle), cosf(angle));
}

// ---------------- GEMM mainloop pieces ----------------
#define TILE_B 10240
#define BUF1_B 20480
#define G1_SMEM (2 * BUF1_B)
#define SPAD 132

__device__ __forceinline__ void tile_async(uint32_t dst, const void* src_,
                                           int ldk, int tid) {
    const __half* src = (const __half*)src_;
#pragma unroll
    for (int t = 0; t < 2; t++) {
        int i = tid + t * 256;
        int r = i >> 2, q = i & 3;
        CP_ASYNC16(dst + r * 80 + q * 16, src + (size_t)r * ldk + q * 8);
    }
}

// single-pass fp16 mainloop (A, B)
#define GEMM_MAINLOOP1(Ah, Bh, K)                                                   \
    const int NC = (K) >> 5;                                                        \
    {                                                                               \
        tile_async(sb,          (Ah) + (size_t)m0 * (K), (K), tid);                 \
        tile_async(sb + TILE_B, (Bh) + (size_t)n0 * (K), (K), tid);                 \
        CP_COMMIT();                                                                \
    }                                                                               \
    for (int c = 0; c < NC; c++) {                                                  \
        CP_WAIT0();                                                                 \
        __syncthreads();                                                            \
        if (c + 1 < NC) {                                                           \
            const uint32_t nb = sb + ((c + 1) & 1) * BUF1_B;                        \
            tile_async(nb,          (Ah) + (size_t)m0 * (K) + (size_t)(c + 1) * 32, (K), tid); \
            tile_async(nb + TILE_B, (Bh) + (size_t)n0 * (K) + (size_t)(c + 1) * 32, (K), tid); \
            CP_COMMIT();                                                            \
        }                                                                           \
        const uint32_t base = sb + (c & 1) * BUF1_B;                                \
        _Pragma("unroll")                                                           \
        for (int ks = 0; ks < 32; ks += 16) {                                       \
            uint32_t ah[4][4], bh[2][4];                                            \
            const uint32_t aoff = (uint32_t)((wm + a_row) * 80 + (ks + a_kh * 8) * 2); \
            const uint32_t boff = (uint32_t)((wn + b_n) * 80 + (ks + b_kh * 8) * 2);   \
            _Pragma("unroll")                                                       \
            for (int mt = 0; mt < 4; mt++)                                          \
                LDSM4(ah[mt][0], ah[mt][1], ah[mt][2], ah[mt][3],                   \
                      base + aoff + mt * 16 * 80);                                  \
            _Pragma("unroll")                                                       \
            for (int np = 0; np < 2; np++)                                          \
                LDSM4(bh[np][0], bh[np][1], bh[np][2], bh[np][3],                   \
                      base + TILE_B + boff + np * 16 * 80);                         \
            _Pragma("unroll")                                                       \
            for (int mt = 0; mt < 4; mt++)                                          \
                _Pragma("unroll")                                                   \
                for (int np = 0; np < 2; np++) {                                    \
                    MMA16816F(acc[mt][np * 2 + 0], ah[mt], bh[np][0], bh[np][1]);   \
                    MMA16816F(acc[mt][np * 2 + 1], ah[mt], bh[np][2], bh[np][3]);   \
                }                                                                   \
        }                                                                           \
    }

// ---------------- QKV GEMM (1-pass) with fused rope/convert epilogue ----------------
__global__ __launch_bounds__(256, 2) void gemm_qkv(
    const __half* __restrict__ Ah, const __half* __restrict__ Bh,
    __half* __restrict__ Qh, __half* __restrict__ Kh, __half* __restrict__ Vh,
    const float2* __restrict__ sc) {
    extern __shared__ char smem[];
    const uint32_t sb = smem_u32(smem);
    const int tid = threadIdx.x;
    const int w = tid >> 5;
    const int lane = tid & 31;
    const int wm = (w & 1) * 64;
    const int wn = (w >> 1) * 32;
    const int m0 = blockIdx.y * 128;
    const int n0 = blockIdx.x * 128;

    const int a_row = lane & 15;
    const int a_kh = (lane >> 4) & 1;
    const int b_n = (lane & 7) + ((lane >> 4) << 3);
    const int b_kh = (lane >> 3) & 1;

    float acc[4][4][4];
#pragma unroll
    for (int i = 0; i < 4; i++)
#pragma unroll
        for (int j = 0; j < 4; j++)
#pragma unroll
            for (int r = 0; r < 4; r++) acc[i][j][r] = 0.f;

    GEMM_MAINLOOP1(Ah, Bh, HID)

    const int g = lane >> 2, c2 = lane & 3;

    if (n0 >= HID + KVD) {
        const int vcol0 = n0 - (HID + KVD);
#pragma unroll
        for (int mt = 0; mt < 4; mt++) {
            const int row = m0 + wm + mt * 16 + g;
#pragma unroll
            for (int nt = 0; nt < 4; nt++) {
                const int col = vcol0 + wn + nt * 8 + c2 * 2;
                __half2 v0 = __floats2half2_rn(acc[mt][nt][0], acc[mt][nt][1]);
                __half2 v1 = __floats2half2_rn(acc[mt][nt][2], acc[mt][nt][3]);
                *(uint32_t*)&Vh[(size_t)row * KVD + col] = *reinterpret_cast<uint32_t*>(&v0);
                *(uint32_t*)&Vh[(size_t)(row + 8) * KVD + col] = *reinterpret_cast<uint32_t*>(&v1);
            }
        }
        return;
    }

    const bool isQ = (n0 < HID);
    const float scale = isQ ? 0.125f : 1.0f;
    float* st = (float*)smem;

#pragma unroll
    for (int h = 0; h < 2; h++) {
        __syncthreads();
#pragma unroll
        for (int mt2 = 0; mt2 < 2; mt2++) {
            const int mt = 2 * h + mt2;
            const int sr = (w & 1) * 32 + mt2 * 16 + g;
#pragma unroll
            for (int nt = 0; nt < 4; nt++) {
                const int col = wn + nt * 8 + c2 * 2;
                st[sr * SPAD + col] = acc[mt][nt][0];
                st[sr * SPAD + col + 1] = acc[mt][nt][1];
                st[(sr + 8) * SPAD + col] = acc[mt][nt][2];
                st[(sr + 8) * SPAD + col + 1] = acc[mt][nt][3];
            }
        }
        __syncthreads();
#pragma unroll
        for (int i = 0; i < 16; i++) {
            const int idx = tid + i * 256;
            const int sr = idx >> 6;
            const int col = (idx & 63) * 2;
            const int br = (sr < 32) ? h * 32 + sr : 64 + h * 32 + (sr - 32);
            const int s = m0 + br;
            const int hl = col & 63;
            const int j = hl & 31;
            const float2 sc0 = sc[s * 32 + j];
            const float2 sc1 = sc[s * 32 + j + 1];
            const float v0 = st[sr * SPAD + col], v1 = st[sr * SPAD + col + 1];
            float r0, r1;
            if (hl < 32) {
                const float b0 = st[sr * SPAD + col + 32], b1 = st[sr * SPAD + col + 33];
                r0 = (v0 * sc0.y + b0 * sc0.x) * scale;
                r1 = (v1 * sc1.y + b1 * sc1.x) * scale;
            } else {
                const float a0 = st[sr * SPAD + col - 32], a1 = st[sr * SPAD + col - 31];
                r0 = (a0 * sc0.x - v0 * sc0.y) * scale;
                r1 = (a1 * sc1.x - v1 * sc1.y) * scale;
            }
            __half2 v = __floats2half2_rn(r0, r1);
            if (isQ) {
                *(uint32_t*)&Qh[(size_t)s * HID + n0 + col] = *reinterpret_cast<uint32_t*>(&v);
            } else {
                *(uint32_t*)&Kh[(size_t)s * KVD + (n0 - HID) + col] =
                    *reinterpret_cast<uint32_t*>(&v);
            }
        }
    }
}

// ---------------- single-pass fp16 GEMM (O projection) ----------------
__global__ __launch_bounds__(256, 2) void gemm_mma1(
    const __half* __restrict__ Ah, const __half* __restrict__ Bh,
    float* __restrict__ C, int M, int N, int K) {
    extern __shared__ char smem[];
    const uint32_t sb = smem_u32(smem);
    const int tid = threadIdx.x;
    const int w = tid >> 5;
    const int lane = tid & 31;
    const int wm = (w & 1) * 64;
    const int wn = (w >> 1) * 32;
    const int m0 = blockIdx.y * 128;
    const int n0 = blockIdx.x * 128;

    const int a_row = lane & 15;
    const int a_kh = (lane >> 4) & 1;
    const int b_n = (lane & 7) + ((lane >> 4) << 3);
    const int b_kh = (lane >> 3) & 1;

    float acc[4][4][4];
#pragma unroll
    for (int i = 0; i < 4; i++)
#pragma unroll
        for (int j = 0; j < 4; j++)
#pragma unroll
            for (int r = 0; r < 4; r++) acc[i][j][r] = 0.f;

    GEMM_MAINLOOP1(Ah, Bh, K)

    const int g = lane >> 2, c2 = lane & 3;
#pragma unroll
    for (int mt = 0; mt < 4; mt++) {
        const int row = m0 + wm + mt * 16 + g;
#pragma unroll
        for (int nt = 0; nt < 4; nt++) {
            const int col = n0 + wn + nt * 8 + c2 * 2;
            *(float2*)&C[(size_t)row * N + col] =
                make_float2(acc[mt][nt][0], acc[mt][nt][1]);
            *(float2*)&C[(size_t)(row + 8) * N + col] =
                make_float2(acc[mt][nt][2], acc[mt][nt][3]);
        }
    }
}

// ---------------- all-fp16 flash attention, single-pass S and PV ----------------
#define FKV  18432
#define FKV_STRIDE 18432
#define F_SMEM 55296

__global__ __launch_bounds__(256, 2) void flash_mma(
    const __half* __restrict__ Qh,
    const __half* __restrict__ Kh, const __half* __restrict__ Vh,
    __half* __restrict__ Oh) {
    extern __shared__ char smem[];
    const uint32_t sb = smem_u32(smem);
    const int tid = threadIdx.x;
    const int lane = tid & 31;
    const int w = tid >> 5;
    const int ib = gridDim.x - 1 - blockIdx.x;
    const int qh = blockIdx.y;
    const int kh = qh >> 2;
    const int qbase = ib * 128;

#pragma unroll
    for (int i = 0; i < 4; i++) {
        int idx = tid + i * 256;
        int r = idx >> 3, q = idx & 7;
        CP_ASYNC16(sb + r * 144 + q * 16,
                   Qh + (size_t)(qbase + r) * HID + qh * 64 + q * 8);
    }
    CP_COMMIT();

#pragma unroll
    for (int i = 0; i < 4; i++) {
        int idx = tid + i * 256;
        int sub = idx >> 9, r = (idx >> 3) & 63, q = idx & 7;
        const __half* base = sub ? Vh : Kh;
        CP_ASYNC16(sb + FKV + sub * 9216 + r * 144 + q * 16,
                   base + (size_t)r * KVD + kh * 64 + q * 8);
    }
    CP_COMMIT();

    const int a_row = lane & 15, a_kh = lane >> 4;
    const int b_n = (lane & 7) + ((lane >> 4) << 3), b_kh = (lane >> 3) & 1;
    const int v_k = (lane & 7) + ((lane >> 3) & 1) * 8, v_n = (lane >> 4) * 8;
    const int g = lane >> 2, tg = lane & 3;

    float o[8][4];
#pragma unroll
    for (int nt = 0; nt < 8; nt++)
#pragma unroll
        for (int r = 0; r < 4; r++) o[nt][r] = 0.f;
    float m0 = -1e30f, m1 = -1e30f, l0 = 0.f, l1 = 0.f;

    const int jbmax = 2 * ib + 1;
    for (int jb = 0; jb <= jbmax; jb++) {
        const uint32_t kvb = sb + FKV + (jb & 1) * FKV_STRIDE;
        __syncthreads();
        if (jb < jbmax) {
            const uint32_t nb = sb + FKV + ((jb + 1) & 1) * FKV_STRIDE;
#pragma unroll
            for (int i = 0; i < 4; i++) {
                int idx = tid + i * 256;
                int sub = idx >> 9, r = (idx >> 3) & 63, q = idx & 7;
                const __half* base = sub ? Vh : Kh;
                CP_ASYNC16(nb + sub * 9216 + r * 144 + q * 16,
                           base + (size_t)((jb + 1) * 64 + r) * KVD + kh * 64 + q * 8);
            }
            CP_COMMIT();
            CP_WAIT1();
        } else {
            CP_WAIT0();
        }
        __syncthreads();

        float s[8][4];
#pragma unroll
        for (int nt = 0; nt < 8; nt++)
#pragma unroll
            for (int r = 0; r < 4; r++) s[nt][r] = 0.f;
#pragma unroll
        for (int kc = 0; kc < 4; kc++) {
            uint32_t ah[4];
            const uint32_t aoff = (w * 16 + a_row) * 144 + (kc * 16 + a_kh * 8) * 2;
            LDSM4(ah[0], ah[1], ah[2], ah[3], sb + aoff);
#pragma unroll
            for (int n2p = 0; n2p < 2; n2p++) {
                uint32_t bh[2][4];
#pragma unroll
                for (int j = 0; j < 2; j++) {
                    const int n2 = n2p * 2 + j;
                    const uint32_t boff = (n2 * 16 + b_n) * 144 + (kc * 16 + b_kh * 8) * 2;
                    LDSM4(bh[j][0], bh[j][1], bh[j][2], bh[j][3], kvb + boff);
                }
#pragma unroll
                for (int j = 0; j < 2; j++) {
                    const int n2 = n2p * 2 + j;
                    MMA16816F(s[n2 * 2 + 0], ah, bh[j][0], bh[j][1]);
                    MMA16816F(s[n2 * 2 + 1], ah, bh[j][2], bh[j][3]);
                }
            }
        }

        if (jb >= 2 * ib) {
            const int row0 = qbase + w * 16 + g;
            const int row1 = row0 + 8;
#pragma unroll
            for (int nt = 0; nt < 8; nt++) {
                const int col = jb * 64 + nt * 8 + tg * 2;
                if (col > row0) s[nt][0] = -1e30f;
                if (col + 1 > row0) s[nt][1] = -1e30f;
                if (col > row1) s[nt][2] = -1e30f;
                if (col + 1 > row1) s[nt][3] = -1e30f;
            }
        }

        float mx0 = -1e30f, mx1 = -1e30f;
#pragma unroll
        for (int nt = 0; nt < 8; nt++) {
            mx0 = fmaxf(mx0, fmaxf(s[nt][0], s[nt][1]));
            mx1 = fmaxf(mx1, fmaxf(s[nt][2], s[nt][3]));
        }
        mx0 = fmaxf(mx0, __shfl_xor_sync(0xffffffff, mx0, 1));
        mx0 = fmaxf(mx0, __shfl_xor_sync(0xffffffff, mx0, 2));
        mx1 = fmaxf(mx1, __shfl_xor_sync(0xffffffff, mx1, 1));
        mx1 = fmaxf(mx1, __shfl_xor_sync(0xffffffff, mx1, 2));
        const float mn0 = fmaxf(m0, mx0), mn1 = fmaxf(m1, mx1);
        const float al0 = __expf(m0 - mn0), al1 = __expf(m1 - mn1);
        m0 = mn0; m1 = mn1;

        float rs0 = 0.f, rs1 = 0.f;
#pragma unroll
        for (int nt = 0; nt < 8; nt++) {
            s[nt][0] = __expf(s[nt][0] - mn0);
            s[nt][1] = __expf(s[nt][1] - mn0);
            s[nt][2] = __expf(s[nt][2] - mn1);
            s[nt][3] = __expf(s[nt][3] - mn1);
            rs0 += s[nt][0] + s[nt][1];
            rs1 += s[nt][2] + s[nt][3];
            o[nt][0] *= al0; o[nt][1] *= al0;
            o[nt][2] *= al1; o[nt][3] *= al1;
        }
        rs0 += __shfl_xor_sync(0xffffffff, rs0, 1);
        rs0 += __shfl_xor_sync(0xffffffff, rs0, 2);
        rs1 += __shfl_xor_sync(0xffffffff, rs1, 1);
        rs1 += __shfl_xor_sync(0xffffffff, rs1, 2);
        l0 = l0 * al0 + rs0;
        l1 = l1 * al1 + rs1;

#pragma unroll
        for (int kc2 = 0; kc2 < 4; kc2++) {
            uint32_t aph[4];
            __half2 p0 = __floats2half2_rn(s[2 * kc2][0], s[2 * kc2][1]);
            __half2 p1 = __floats2half2_rn(s[2 * kc2][2], s[2 * kc2][3]);
            __half2 p2 = __floats2half2_rn(s[2 * kc2 + 1][0], s[2 * kc2 + 1][1]);
            __half2 p3 = __floats2half2_rn(s[2 * kc2 + 1][2], s[2 * kc2 + 1][3]);
            aph[0] = *reinterpret_cast<uint32_t*>(&p0);
            aph[1] = *reinterpret_cast<uint32_t*>(&p1);
            aph[2] = *reinterpret_cast<uint32_t*>(&p2);
            aph[3] = *reinterpret_cast<uint32_t*>(&p3);
#pragma unroll
            for (int n2p = 0; n2p < 2; n2p++) {
                uint32_t vh[2][4];
#pragma unroll
                for (int j = 0; j < 2; j++) {
                    const int n2 = n2p * 2 + j;
                    const uint32_t voff = (kc2 * 16 + v_k) * 144 + (n2 * 16 + v_n) * 2;
                    LDSM4T(vh[j][0], vh[j][1], vh[j][2], vh[j][3], kvb + 9216 + voff);
                }
#pragma unroll
                for (int j = 0; j < 2; j++) {
                    const int n2 = n2p * 2 + j;
                    MMA16816F(o[n2 * 2 + 0], aph, vh[j][0], vh[j][1]);
                    MMA16816F(o[n2 * 2 + 1], aph, vh[j][2], vh[j][3]);
                }
            }
        }
    }

    const float il0 = 1.0f / l0, il1 = 1.0f / l1;
    const int row0 = qbase + w * 16 + g;
#pragma unroll
    for (int nt = 0; nt < 8; nt++) {
        const int col = qh * 64 + nt * 8 + tg * 2;
        __half2 v0 = __floats2half2_rn(o[nt][0] * il0, o[nt][1] * il0);
        __half2 v1 = __floats2half2_rn(o[nt][2] * il1, o[nt][3] * il1);
        *(uint32_t*)&Oh[(size_t)row0 * HID + col] = *reinterpret_cast<uint32_t*>(&v0);
        *(uint32_t*)&Oh[(size_t)(row0 + 8) * HID + col] = *reinterpret_cast<uint32_t*>(&v1);
    }
}

// ---------------------------------------------------------------------------
extern "C" void kernel_launch(void* const* d_in, const int* in_sizes, int n_in,
                              void* d_out, int out_size) {
    const float* x        = (const float*)d_in[0];
    const float* q_proj   = (const float*)d_in[1];
    const float* k_proj   = (const float*)d_in[2];
    const float* v_proj   = (const float*)d_in[3];
    const float* o_proj   = (const float*)d_in[4];
    const float* inv_freq = (const float*)d_in[5];
    float* out = (float*)d_out;

    __half *Axh, *Qh, *Oh, *Wh, *Kh, *Vh;
    float2* sc;
    cudaGetSymbolAddress((void**)&Axh, g_Axh);
    cudaGetSymbolAddress((void**)&Qh, g_Qh);
    cudaGetSymbolAddress((void**)&Oh, g_Oh);
    cudaGetSymbolAddress((void**)&Wh, g_Wh);
    cudaGetSymbolAddress((void**)&Kh, g_Kh);
    cudaGetSymbolAddress((void**)&Vh, g_Vh);
    cudaGetSymbolAddress((void**)&sc, g_sc);

    cudaFuncSetAttribute(gemm_qkv, cudaFuncAttributeMaxDynamicSharedMemorySize, G1_SMEM);
    cudaFuncSetAttribute(gemm_mma1, cudaFuncAttributeMaxDynamicSharedMemorySize, G1_SMEM);
    cudaFuncSetAttribute(flash_mma, cudaFuncAttributeMaxDynamicSharedMemorySize, F_SMEM);

    const int convBlocks = (SEQ * HID / 4) / 256;

    convert_h16<<<convBlocks, 256>>>(x, Axh);
    transpose_all16<<<dim3(160, HID / 32), 256>>>(q_proj, k_proj, v_proj, o_proj, Wh);
    sc_init<<<SEQ * 32 / 256, 256>>>(inv_freq, sc);

    // fused QKV projection + rope + fp16 convert (single fp16 pass)
    gemm_qkv<<<dim3(QKVN / 128, SEQ / 128), 256, G1_SMEM>>>(Axh, Wh, Qh, Kh, Vh, sc);

    // all-fp16 flash attention (single-pass S, single-pass PV)
    flash_mma<<<dim3(SEQ / 128, NQH), 256, F_SMEM>>>(Qh, Kh, Vh, Oh);

    // out = O @ o_proj (single-pass fp16)
    gemm_mma1<<<dim3(HID / 128, SEQ / 128), 256, G1_SMEM>>>(Oh, Wh + (size_t)QKVN * HID,
                                                            out, SEQ, HID, HID);
}

// round 17
// speedup vs baseline: 1.6353x; 1.0079x over previous
#include <cuda_runtime.h>
#include <cuda_fp16.h>
#include <math.h>
#include <cstdint>

#define SEQ 2048
#define HID 2048
#define KVD 512
#define QKVN 3072
#define WROWS 5120
#define NQH 32
#define NKH 8

// ---------------- scratch (no allocations allowed) ----------------
__device__ __half g_Axh[SEQ * HID];          // x fp16
__device__ __half g_Qh[SEQ * HID];           // Q fp16 (post-rope, scaled)
__device__ __half g_Oh[SEQ * HID];           // attention output fp16
__device__ __half g_Wh[WROWS * HID];         // transposed q|k|v|o weights, fp16
__device__ __half g_Kh[SEQ * KVD];           // K fp16 (post-rope)
__device__ __half g_Vh[SEQ * KVD];           // V fp16
__device__ float2 g_sc[SEQ * 32];            // sincos LUT

// ---------------- helpers ----------------
__device__ __forceinline__ uint32_t smem_u32(const void* p) {
    uint32_t a;
    asm("{ .reg .u64 t; cvta.to.shared.u64 t, %1; cvt.u32.u64 %0, t; }" : "=r"(a) : "l"(p));
    return a;
}

#define LDSM4(r0, r1, r2, r3, addr) \
    asm volatile("ldmatrix.sync.aligned.m8n8.x4.shared.b16 {%0,%1,%2,%3}, [%4];" \
        : "=r"(r0), "=r"(r1), "=r"(r2), "=r"(r3) : "r"(addr))

#define LDSM4T(r0, r1, r2, r3, addr) \
    asm volatile("ldmatrix.sync.aligned.m8n8.x4.trans.shared.b16 {%0,%1,%2,%3}, [%4];" \
        : "=r"(r0), "=r"(r1), "=r"(r2), "=r"(r3) : "r"(addr))

#define MMA16816F(d, a, b0, b1) \
    asm volatile("mma.sync.aligned.m16n8k16.row.col.f32.f16.f16.f32 " \
        "{%0,%1,%2,%3},{%4,%5,%6,%7},{%8,%9},{%0,%1,%2,%3};" \
        : "+f"((d)[0]), "+f"((d)[1]), "+f"((d)[2]), "+f"((d)[3]) \
        : "r"((a)[0]), "r"((a)[1]), "r"((a)[2]), "r"((a)[3]), "r"(b0), "r"(b1))

#define CP_ASYNC16(dst, src) \
    asm volatile("cp.async.cg.shared.global [%0], [%1], 16;" :: "r"(dst), "l"(src))
#define CP_COMMIT() asm volatile("cp.async.commit_group;" ::: "memory")
#define CP_WAIT0()  asm volatile("cp.async.wait_group 0;" ::: "memory")
#define CP_WAIT1()  asm volatile("cp.async.wait_group 1;" ::: "memory")

// ---------------- fused prologue: convert x | transpose weights | sincos LUT ----------------
#define PRO_CONV 4096
#define PRO_TRAN 10240
#define PRO_SC 256

__global__ __launch_bounds__(256) void prologue(
    const float* __restrict__ X,
    const float* __restrict__ Wq, const float* __restrict__ Wk,
    const float* __restrict__ Wv, const float* __restrict__ Wo,
    const float* __restrict__ inv_freq,
    __half* __restrict__ Axh, __half* __restrict__ toh, float2* __restrict__ sc) {
    __shared__ float t[32][33];
    const int b = blockIdx.x;
    const int tid = threadIdx.x;

    if (b < PRO_CONV) {
        // x fp32 -> fp16
        int i = b * 256 + tid;
        float4 v = *(const float4*)(X + (size_t)i * 4);
        __half2 a = __floats2half2_rn(v.x, v.y);
        __half2 c = __floats2half2_rn(v.z, v.w);
        *(uint2*)(Axh + (size_t)i * 4) =
            make_uint2(*reinterpret_cast<uint32_t*>(&a), *reinterpret_cast<uint32_t*>(&c));
    } else if (b < PRO_CONV + PRO_TRAN) {
        // weight transpose -> fp16 [WROWS, HID]
        const int idx = b - PRO_CONV;
        const int bx = idx % 160;
        const int by = idx / 160;
        const float* W;
        int N, nblk, dstoff;
        if (bx < 64)       { W = Wq; N = HID; nblk = bx;      dstoff = 0; }
        else if (bx < 80)  { W = Wk; N = KVD; nblk = bx - 64; dstoff = HID; }
        else if (bx < 96)  { W = Wv; N = KVD; nblk = bx - 80; dstoff = HID + KVD; }
        else               { W = Wo; N = HID; nblk = bx - 96; dstoff = QKVN; }
        int tx = tid & 31, ty = tid >> 5;
        int k0 = by * 32, n0 = nblk * 32;
#pragma unroll
        for (int i = 0; i < 4; i++)
            t[ty + i * 8][tx] = W[(size_t)(k0 + ty + i * 8) * N + n0 + tx];
        __syncthreads();
#pragma unroll
        for (int i = 0; i < 4; i++) {
            float v = t[tx][ty + i * 8];
            toh[(size_t)(dstoff + n0 + ty + i * 8) * HID + k0 + tx] = __float2half_rn(v);
        }
    } else {
        // sincos LUT
        int i = (b - PRO_CONV - PRO_TRAN) * 256 + tid;
        int s = i >> 5, j = i & 31;
        float angle = (float)s * inv_freq[j];
        sc[i] = make_float2(sinf(angle), cosf(angle));
    }
}

// ---------------- GEMM mainloop pieces ----------------
#define TILE_B 10240
#define BUF1_B 20480
#define G1_SMEM (2 * BUF1_B)
#define SPAD 132

__device__ __forceinline__ void tile_async(uint32_t dst, const void* src_,
                                           int ldk, int tid) {
    const __half* src = (const __half*)src_;
#pragma unroll
    for (int t = 0; t < 2; t++) {
        int i = tid + t * 256;
        int r = i >> 2, q = i & 3;
        CP_ASYNC16(dst + r * 80 + q * 16, src + (size_t)r * ldk + q * 8);
    }
}

#define GEMM_MAINLOOP1(Ah, Bh, K)                                                   \
    const int NC = (K) >> 5;                                                        \
    {                                                                               \
        tile_async(sb,          (Ah) + (size_t)m0 * (K), (K), tid);                 \
        tile_async(sb + TILE_B, (Bh) + (size_t)n0 * (K), (K), tid);                 \
        CP_COMMIT();                                                                \
    }                                                                               \
    for (int c = 0; c < NC; c++) {                                                  \
        CP_WAIT0();                                                                 \
        __syncthreads();                                                            \
        if (c + 1 < NC) {                                                           \
            const uint32_t nb = sb + ((c + 1) & 1) * BUF1_B;                        \
            tile_async(nb,          (Ah) + (size_t)m0 * (K) + (size_t)(c + 1) * 32, (K), tid); \
            tile_async(nb + TILE_B, (Bh) + (size_t)n0 * (K) + (size_t)(c + 1) * 32, (K), tid); \
            CP_COMMIT();                                                            \
        }                                                                           \
        const uint32_t base = sb + (c & 1) * BUF1_B;                                \
        _Pragma("unroll")                                                           \
        for (int ks = 0; ks < 32; ks += 16) {                                       \
            uint32_t ah[4][4], bh[2][4];                                            \
            const uint32_t aoff = (uint32_t)((wm + a_row) * 80 + (ks + a_kh * 8) * 2); \
            const uint32_t boff = (uint32_t)((wn + b_n) * 80 + (ks + b_kh * 8) * 2);   \
            _Pragma("unroll")                                                       \
            for (int mt = 0; mt < 4; mt++)                                          \
                LDSM4(ah[mt][0], ah[mt][1], ah[mt][2], ah[mt][3],                   \
                      base + aoff + mt * 16 * 80);                                  \
            _Pragma("unroll")                                                       \
            for (int np = 0; np < 2; np++)                                          \
                LDSM4(bh[np][0], bh[np][1], bh[np][2], bh[np][3],                   \
                      base + TILE_B + boff + np * 16 * 80);                         \
            _Pragma("unroll")                                                       \
            for (int mt = 0; mt < 4; mt++)                                          \
                _Pragma("unroll")                                                   \
                for (int np = 0; np < 2; np++) {                                    \
                    MMA16816F(acc[mt][np * 2 + 0], ah[mt], bh[np][0], bh[np][1]);   \
                    MMA16816F(acc[mt][np * 2 + 1], ah[mt], bh[np][2], bh[np][3]);   \
                }                                                                   \
        }                                                                           \
    }

// ---------------- QKV GEMM (1-pass) with fused rope/convert epilogue ----------------
__global__ __launch_bounds__(256, 2) void gemm_qkv(
    const __half* __restrict__ Ah, const __half* __restrict__ Bh,
    __half* __restrict__ Qh, __half* __restrict__ Kh, __half* __restrict__ Vh,
    const float2* __restrict__ sc) {
    extern __shared__ char smem[];
    const uint32_t sb = smem_u32(smem);
    const int tid = threadIdx.x;
    const int w = tid >> 5;
    const int lane = tid & 31;
    const int wm = (w & 1) * 64;
    const int wn = (w >> 1) * 32;
    const int m0 = blockIdx.y * 128;
    const int n0 = blockIdx.x * 128;

    const int a_row = lane & 15;
    const int a_kh = (lane >> 4) & 1;
    const int b_n = (lane & 7) + ((lane >> 4) << 3);
    const int b_kh = (lane >> 3) & 1;

    float acc[4][4][4];
#pragma unroll
    for (int i = 0; i < 4; i++)
#pragma unroll
        for (int j = 0; j < 4; j++)
#pragma unroll
            for (int r = 0; r < 4; r++) acc[i][j][r] = 0.f;

    GEMM_MAINLOOP1(Ah, Bh, HID)

    const int g = lane >> 2, c2 = lane & 3;

    if (n0 >= HID + KVD) {
        const int vcol0 = n0 - (HID + KVD);
#pragma unroll
        for (int mt = 0; mt < 4; mt++) {
            const int row = m0 + wm + mt * 16 + g;
#pragma unroll
            for (int nt = 0; nt < 4; nt++) {
                const int col = vcol0 + wn + nt * 8 + c2 * 2;
                __half2 v0 = __floats2half2_rn(acc[mt][nt][0], acc[mt][nt][1]);
                __half2 v1 = __floats2half2_rn(acc[mt][nt][2], acc[mt][nt][3]);
                *(uint32_t*)&Vh[(size_t)row * KVD + col] = *reinterpret_cast<uint32_t*>(&v0);
                *(uint32_t*)&Vh[(size_t)(row + 8) * KVD + col] = *reinterpret_cast<uint32_t*>(&v1);
            }
        }
        return;
    }

    const bool isQ = (n0 < HID);
    const float scale = isQ ? 0.125f : 1.0f;
    float* st = (float*)smem;

#pragma unroll
    for (int h = 0; h < 2; h++) {
        __syncthreads();
#pragma unroll
        for (int mt2 = 0; mt2 < 2; mt2++) {
            const int mt = 2 * h + mt2;
            const int sr = (w & 1) * 32 + mt2 * 16 + g;
#pragma unroll
            for (int nt = 0; nt < 4; nt++) {
                const int col = wn + nt * 8 + c2 * 2;
                st[sr * SPAD + col] = acc[mt][nt][0];
                st[sr * SPAD + col + 1] = acc[mt][nt][1];
                st[(sr + 8) * SPAD + col] = acc[mt][nt][2];
                st[(sr + 8) * SPAD + col + 1] = acc[mt][nt][3];
            }
        }
        __syncthreads();
#pragma unroll
        for (int i = 0; i < 16; i++) {
            const int idx = tid + i * 256;
            const int sr = idx >> 6;
            const int col = (idx & 63) * 2;
            const int br = (sr < 32) ? h * 32 + sr : 64 + h * 32 + (sr - 32);
            const int s = m0 + br;
            const int hl = col & 63;
            const int j = hl & 31;
            const float2 sc0 = sc[s * 32 + j];
            const float2 sc1 = sc[s * 32 + j + 1];
            const float v0 = st[sr * SPAD + col], v1 = st[sr * SPAD + col + 1];
            float r0, r1;
            if (hl < 32) {
                const float b0 = st[sr * SPAD + col + 32], b1 = st[sr * SPAD + col + 33];
                r0 = (v0 * sc0.y + b0 * sc0.x) * scale;
                r1 = (v1 * sc1.y + b1 * sc1.x) * scale;
            } else {
                const float a0 = st[sr * SPAD + col - 32], a1 = st[sr * SPAD + col - 31];
                r0 = (a0 * sc0.x - v0 * sc0.y) * scale;
                r1 = (a1 * sc1.x - v1 * sc1.y) * scale;
            }
            __half2 v = __floats2half2_rn(r0, r1);
            if (isQ) {
                *(uint32_t*)&Qh[(size_t)s * HID + n0 + col] = *reinterpret_cast<uint32_t*>(&v);
            } else {
                *(uint32_t*)&Kh[(size_t)s * KVD + (n0 - HID) + col] =
                    *reinterpret_cast<uint32_t*>(&v);
            }
        }
    }
}

// ---------------- single-pass fp16 GEMM (O projection) ----------------
__global__ __launch_bounds__(256, 2) void gemm_mma1(
    const __half* __restrict__ Ah, const __half* __restrict__ Bh,
    float* __restrict__ C, int M, int N, int K) {
    extern __shared__ char smem[];
    const uint32_t sb = smem_u32(smem);
    const int tid = threadIdx.x;
    const int w = tid >> 5;
    const int lane = tid & 31;
    const int wm = (w & 1) * 64;
    const int wn = (w >> 1) * 32;
    const int m0 = blockIdx.y * 128;
    const int n0 = blockIdx.x * 128;

    const int a_row = lane & 15;
    const int a_kh = (lane >> 4) & 1;
    const int b_n = (lane & 7) + ((lane >> 4) << 3);
    const int b_kh = (lane >> 3) & 1;

    float acc[4][4][4];
#pragma unroll
    for (int i = 0; i < 4; i++)
#pragma unroll
        for (int j = 0; j < 4; j++)
#pragma unroll
            for (int r = 0; r < 4; r++) acc[i][j][r] = 0.f;

    GEMM_MAINLOOP1(Ah, Bh, K)

    const int g = lane >> 2, c2 = lane & 3;
#pragma unroll
    for (int mt = 0; mt < 4; mt++) {
        const int row = m0 + wm + mt * 16 + g;
#pragma unroll
        for (int nt = 0; nt < 4; nt++) {
            const int col = n0 + wn + nt * 8 + c2 * 2;
            *(float2*)&C[(size_t)row * N + col] =
                make_float2(acc[mt][nt][0], acc[mt][nt][1]);
            *(float2*)&C[(size_t)(row + 8) * N + col] =
                make_float2(acc[mt][nt][2], acc[mt][nt][3]);
        }
    }
}

// ---------------- all-fp16 flash attention with diagonal-tile skipping ----------------
#define FKV  18432
#define FKV_STRIDE 18432
#define F_SMEM 55296

__global__ __launch_bounds__(256, 2) void flash_mma(
    const __half* __restrict__ Qh,
    const __half* __restrict__ Kh, const __half* __restrict__ Vh,
    __half* __restrict__ Oh) {
    extern __shared__ char smem[];
    const uint32_t sb = smem_u32(smem);
    const int tid = threadIdx.x;
    const int lane = tid & 31;
    const int w = tid >> 5;
    const int ib = gridDim.x - 1 - blockIdx.x;
    const int qh = blockIdx.y;
    const int kh = qh >> 2;
    const int qbase = ib * 128;

#pragma unroll
    for (int i = 0; i < 4; i++) {
        int idx = tid + i * 256;
        int r = idx >> 3, q = idx & 7;
        CP_ASYNC16(sb + r * 144 + q * 16,
                   Qh + (size_t)(qbase + r) * HID + qh * 64 + q * 8);
    }
    CP_COMMIT();

#pragma unroll
    for (int i = 0; i < 4; i++) {
        int idx = tid + i * 256;
        int sub = idx >> 9, r = (idx >> 3) & 63, q = idx & 7;
        const __half* base = sub ? Vh : Kh;
        CP_ASYNC16(sb + FKV + sub * 9216 + r * 144 + q * 16,
                   base + (size_t)r * KVD + kh * 64 + q * 8);
    }
    CP_COMMIT();

    const int a_row = lane & 15, a_kh = lane >> 4;
    const int b_n = (lane & 7) + ((lane >> 4) << 3), b_kh = (lane >> 3) & 1;
    const int v_k = (lane & 7) + ((lane >> 3) & 1) * 8, v_n = (lane >> 4) * 8;
    const int g = lane >> 2, tg = lane & 3;

    float o[8][4];
#pragma unroll
    for (int nt = 0; nt < 8; nt++)
#pragma unroll
        for (int r = 0; r < 4; r++) o[nt][r] = 0.f;
    float m0 = -1e30f, m1 = -1e30f, l0 = 0.f, l1 = 0.f;

    const int jbmax = 2 * ib + 1;
    for (int jb = 0; jb <= jbmax; jb++) {
        const uint32_t kvb = sb + FKV + (jb & 1) * FKV_STRIDE;
        __syncthreads();
        if (jb < jbmax) {
            const uint32_t nb = sb + FKV + ((jb + 1) & 1) * FKV_STRIDE;
#pragma unroll
            for (int i = 0; i < 4; i++) {
                int idx = tid + i * 256;
                int sub = idx >> 9, r = (idx >> 3) & 63, q = idx & 7;
                const __half* base = sub ? Vh : Kh;
                CP_ASYNC16(nb + sub * 9216 + r * 144 + q * 16,
                           base + (size_t)((jb + 1) * 64 + r) * KVD + kh * 64 + q * 8);
            }
            CP_COMMIT();
            CP_WAIT1();
        } else {
            CP_WAIT0();
        }
        __syncthreads();

        // diagonal-tile skip flags (warp-uniform; bit-exact transformations)
        const bool firstdiag = (jb == 2 * ib);
        const bool fullskip = (jb == jbmax) && (w < 4);   // rows fully masked

        if (!fullskip) {
            // S = Q K^T (single fp16 pass), skipping fully-masked n2 tiles
            float s[8][4];
#pragma unroll
            for (int nt = 0; nt < 8; nt++)
#pragma unroll
                for (int r = 0; r < 4; r++) s[nt][r] = 0.f;
#pragma unroll
            for (int kc = 0; kc < 4; kc++) {
                uint32_t ah[4];
                const uint32_t aoff = (w * 16 + a_row) * 144 + (kc * 16 + a_kh * 8) * 2;
                LDSM4(ah[0], ah[1], ah[2], ah[3], sb + aoff);
#pragma unroll
                for (int n2 = 0; n2 < 4; n2++) {
                    if (firstdiag && n2 > w) continue;   // tile fully masked
                    uint32_t bh[4];
                    const uint32_t boff = (n2 * 16 + b_n) * 144 + (kc * 16 + b_kh * 8) * 2;
                    LDSM4(bh[0], bh[1], bh[2], bh[3], kvb + boff);
                    MMA16816F(s[n2 * 2 + 0], ah, bh[0], bh[1]);
                    MMA16816F(s[n2 * 2 + 1], ah, bh[2], bh[3]);
                }
            }

            if (jb >= 2 * ib) {
                const int row0 = qbase + w * 16 + g;
                const int row1 = row0 + 8;
#pragma unroll
                for (int nt = 0; nt < 8; nt++) {
                    const int col = jb * 64 + nt * 8 + tg * 2;
                    if (col > row0) s[nt][0] = -1e30f;
                    if (col + 1 > row0) s[nt][1] = -1e30f;
                    if (col > row1) s[nt][2] = -1e30f;
                    if (col + 1 > row1) s[nt][3] = -1e30f;
                }
            }

            float mx0 = -1e30f, mx1 = -1e30f;
#pragma unroll
            for (int nt = 0; nt < 8; nt++) {
                mx0 = fmaxf(mx0, fmaxf(s[nt][0], s[nt][1]));
                mx1 = fmaxf(mx1, fmaxf(s[nt][2], s[nt][3]));
            }
            mx0 = fmaxf(mx0, __shfl_xor_sync(0xffffffff, mx0, 1));
            mx0 = fmaxf(mx0, __shfl_xor_sync(0xffffffff, mx0, 2));
            mx1 = fmaxf(mx1, __shfl_xor_sync(0xffffffff, mx1, 1));
            mx1 = fmaxf(mx1, __shfl_xor_sync(0xffffffff, mx1, 2));
            const float mn0 = fmaxf(m0, mx0), mn1 = fmaxf(m1, mx1);
            const float al0 = __expf(m0 - mn0), al1 = __expf(m1 - mn1);
            m0 = mn0; m1 = mn1;

            float rs0 = 0.f, rs1 = 0.f;
#pragma unroll
            for (int nt = 0; nt < 8; nt++) {
                s[nt][0] = __expf(s[nt][0] - mn0);
                s[nt][1] = __expf(s[nt][1] - mn0);
                s[nt][2] = __expf(s[nt][2] - mn1);
                s[nt][3] = __expf(s[nt][3] - mn1);
                rs0 += s[nt][0] + s[nt][1];
                rs1 += s[nt][2] + s[nt][3];
                o[nt][0] *= al0; o[nt][1] *= al0;
                o[nt][2] *= al1; o[nt][3] *= al1;
            }
            rs0 += __shfl_xor_sync(0xffffffff, rs0, 1);
            rs0 += __shfl_xor_sync(0xffffffff, rs0, 2);
            rs1 += __shfl_xor_sync(0xffffffff, rs1, 1);
            rs1 += __shfl_xor_sync(0xffffffff, rs1, 2);
            l0 = l0 * al0 + rs0;
            l1 = l1 * al1 + rs1;

            // O += P @ V : single fp16 pass, skipping zero-P kc2 chunks
#pragma unroll
            for (int kc2 = 0; kc2 < 4; kc2++) {
                if (firstdiag && kc2 > w) continue;   // P identically zero
                uint32_t aph[4];
                __half2 p0 = __floats2half2_rn(s[2 * kc2][0], s[2 * kc2][1]);
                __half2 p1 = __floats2half2_rn(s[2 * kc2][2], s[2 * kc2][3]);
                __half2 p2 = __floats2half2_rn(s[2 * kc2 + 1][0], s[2 * kc2 + 1][1]);
                __half2 p3 = __floats2half2_rn(s[2 * kc2 + 1][2], s[2 * kc2 + 1][3]);
                aph[0] = *reinterpret_cast<uint32_t*>(&p0);
                aph[1] = *reinterpret_cast<uint32_t*>(&p1);
                aph[2] = *reinterpret_cast<uint32_t*>(&p2);
                aph[3] = *reinterpret_cast<uint32_t*>(&p3);
#pragma unroll
                for (int n2p = 0; n2p < 2; n2p++) {
                    uint32_t vh[2][4];
#pragma unroll
                    for (int j = 0; j < 2; j++) {
                        const int n2 = n2p * 2 + j;
                        const uint32_t voff = (kc2 * 16 + v_k) * 144 + (n2 * 16 + v_n) * 2;
                        LDSM4T(vh[j][0], vh[j][1], vh[j][2], vh[j][3], kvb + 9216 + voff);
                    }
#pragma unroll
                    for (int j = 0; j < 2; j++) {
                        const int n2 = n2p * 2 + j;
                        MMA16816F(o[n2 * 2 + 0], aph, vh[j][0], vh[j][1]);
                        MMA16816F(o[n2 * 2 + 1], aph, vh[j][2], vh[j][3]);
                    }
                }
            }
        }
    }

    const float il0 = 1.0f / l0, il1 = 1.0f / l1;
    const int row0 = qbase + w * 16 + g;
#pragma unroll
    for (int nt = 0; nt < 8; nt++) {
        const int col = qh * 64 + nt * 8 + tg * 2;
        __half2 v0 = __floats2half2_rn(o[nt][0] * il0, o[nt][1] * il0);
        __half2 v1 = __floats2half2_rn(o[nt][2] * il1, o[nt][3] * il1);
        *(uint32_t*)&Oh[(size_t)row0 * HID + col] = *reinterpret_cast<uint32_t*>(&v0);
        *(uint32_t*)&Oh[(size_t)(row0 + 8) * HID + col] = *reinterpret_cast<uint32_t*>(&v1);
    }
}

// ---------------------------------------------------------------------------
extern "C" void kernel_launch(void* const* d_in, const int* in_sizes, int n_in,
                              void* d_out, int out_size) {
    const float* x        = (const float*)d_in[0];
    const float* q_proj   = (const float*)d_in[1];
    const float* k_proj   = (const float*)d_in[2];
    const float* v_proj   = (const float*)d_in[3];
    const float* o_proj   = (const float*)d_in[4];
    const float* inv_freq = (const float*)d_in[5];
    float* out = (float*)d_out;

    __half *Axh, *Qh, *Oh, *Wh, *Kh, *Vh;
    float2* sc;
    cudaGetSymbolAddress((void**)&Axh, g_Axh);
    cudaGetSymbolAddress((void**)&Qh, g_Qh);
    cudaGetSymbolAddress((void**)&Oh, g_Oh);
    cudaGetSymbolAddress((void**)&Wh, g_Wh);
    cudaGetSymbolAddress((void**)&Kh, g_Kh);
    cudaGetSymbolAddress((void**)&Vh, g_Vh);
    cudaGetSymbolAddress((void**)&sc, g_sc);

    cudaFuncSetAttribute(gemm_qkv, cudaFuncAttributeMaxDynamicSharedMemorySize, G1_SMEM);
    cudaFuncSetAttribute(gemm_mma1, cudaFuncAttributeMaxDynamicSharedMemorySize, G1_SMEM);
    cudaFuncSetAttribute(flash_mma, cudaFuncAttributeMaxDynamicSharedMemorySize, F_SMEM);

    // fused prologue: x convert | weight transpose | sincos LUT
    prologue<<<PRO_CONV + PRO_TRAN + PRO_SC, 256>>>(x, q_proj, k_proj, v_proj, o_proj,
                                                    inv_freq, Axh, Wh, sc);

    // fused QKV projection + rope + fp16 convert (single fp16 pass)
    gemm_qkv<<<dim3(QKVN / 128, SEQ / 128), 256, G1_SMEM>>>(Axh, Wh, Qh, Kh, Vh, sc);

    // all-fp16 flash attention (single-pass S/PV, diagonal tiles skipped)
    flash_mma<<<dim3(SEQ / 128, NQH), 256, F_SMEM>>>(Qh, Kh, Vh, Oh);

    // out = O @ o_proj (single-pass fp16)
    gemm_mma1<<<dim3(HID / 128, SEQ / 128), 256, G1_SMEM>>>(Oh, Wh + (size_t)QKVN * HID,
                                                            out, SEQ, HID, HID);
}